// round 1
// baseline (speedup 1.0000x reference)
#include <cuda_runtime.h>
#include <math.h>

// ---------------- problem constants ----------------
#define B_    4
#define S_    2048
#define DIM_  1024
#define NH_   8
#define DH_   128
#define CS_   16
#define NS_   128
#define BH_   (B_*NH_)        // 32
#define NCHUNK (BH_*NS_)      // 4096
#define EPS_    1e-6f
#define LN_EPS_ 1e-5f
#define NEG_   -1e30f

// ---------------- scratch (device globals; no allocation) ----------------
__device__ float g_ig   [BH_*S_];
__device__ float g_fg   [BH_*S_];
__device__ float g_lfacc[BH_*S_];
__device__ float g_gexp [BH_*S_];
__device__ float g_lfl  [NCHUNK];
__device__ float g_mloc [NCHUNK];
__device__ float g_mp   [NCHUNK];
__device__ float g_a    [NCHUNK];
__device__ float g_b    [NCHUNK];
__device__ float g_kv   [(size_t)NCHUNK*DH_*DH_];  // 256MB: kv, then Cp in-place
__device__ float g_ksum [NCHUNK*DH_];              // ksum, then np in-place

// ============================================================
// K1: gates.  ig/fg[b,h,s] = <[q|k|v](b,s,:), W[h,:]> + bias
// Block handles 8 consecutive positions; gate_in staged in smem
// one 1024-segment at a time (32KB static smem). Warp w = head w.
// ============================================================
#define K1_T 8
__global__ __launch_bounds__(256) void k_gates(
    const float* __restrict__ q, const float* __restrict__ k,
    const float* __restrict__ v, const float* __restrict__ Wi,
    const float* __restrict__ bi, const float* __restrict__ Wf,
    const float* __restrict__ bf)
{
    __shared__ float sg[K1_T][1024];
    int tid  = threadIdx.x;
    int base = blockIdx.x * K1_T;            // flattened (b*S + s)
    int w    = tid >> 5;                     // head
    int lane = tid & 31;
    const float* wi = Wi + w*3072;
    const float* wf = Wf + w*3072;

    float acc_i[K1_T], acc_f[K1_T];
#pragma unroll
    for (int t = 0; t < K1_T; t++) { acc_i[t] = 0.f; acc_f[t] = 0.f; }

    for (int seg = 0; seg < 3; seg++) {
        const float* src = (seg == 0) ? q : (seg == 1) ? k : v;
        for (int r = tid; r < K1_T*1024; r += 256) {
            int t = r >> 10, d = r & 1023;
            sg[t][d] = src[(size_t)(base + t)*1024 + d];
        }
        __syncthreads();
        for (int kk = lane; kk < 1024; kk += 32) {
            float wiv = wi[seg*1024 + kk];
            float wfv = wf[seg*1024 + kk];
#pragma unroll
            for (int t = 0; t < K1_T; t++) {
                float g = sg[t][kk];
                acc_i[t] = fmaf(g, wiv, acc_i[t]);
                acc_f[t] = fmaf(g, wfv, acc_f[t]);
            }
        }
        __syncthreads();
    }
#pragma unroll
    for (int t = 0; t < K1_T; t++) {
#pragma unroll
        for (int off = 16; off; off >>= 1) {
            acc_i[t] += __shfl_xor_sync(0xffffffffu, acc_i[t], off);
            acc_f[t] += __shfl_xor_sync(0xffffffffu, acc_f[t], off);
        }
    }
    if (lane == 0) {
        float biv = bi[w], bfv = bf[w];
#pragma unroll
        for (int t = 0; t < K1_T; t++) {
            int bs = base + t;
            int b = bs >> 11, s = bs & 2047;
            int idx = (b*NH_ + w)*S_ + s;
            g_ig[idx] = acc_i[t] + biv;
            g_fg[idx] = acc_f[t] + bfv;
        }
    }
}

// ============================================================
// K2: per-chunk gate prep. One warp per chunk (lanes 0..15 active).
// lf=logsigmoid(fg), lfacc=cumsum, lfl, lg=ig-lfacc+lfl, m_loc, gexp.
// ============================================================
__global__ __launch_bounds__(128) void k_chunkprep()
{
    int gwarp = (blockIdx.x * blockDim.x + threadIdx.x) >> 5;
    int lane  = threadIdx.x & 31;
    if (gwarp >= NCHUNK) return;
    int bh = gwarp / NS_, n = gwarp % NS_;
    int c  = lane & 15;
    int s  = n*CS_ + c;

    float igv = 0.f, lf = 0.f;
    if (lane < 16) {
        float fgv = g_fg[bh*S_ + s];
        igv = g_ig[bh*S_ + s];
        lf  = fminf(fgv, 0.f) - log1pf(expf(-fabsf(fgv)));
    }
    // inclusive scan over 16-lane segment
    float acc = lf;
#pragma unroll
    for (int off = 1; off < 16; off <<= 1) {
        float t = __shfl_up_sync(0xffffffffu, acc, off, 16);
        if (c >= off) acc += t;
    }
    float lfl = __shfl_sync(0xffffffffu, acc, 15, 16);
    float lg  = igv - acc + lfl;
    float m   = lg;
#pragma unroll
    for (int off = 8; off; off >>= 1)
        m = fmaxf(m, __shfl_xor_sync(0xffffffffu, m, off, 16));
    if (lane < 16) {
        g_lfacc[bh*S_ + s] = acc;
        g_gexp [bh*S_ + s] = expf(lg - m);
        if (lane == 0) { g_lfl[gwarp] = lfl; g_mloc[gwarp] = m; }
    }
}

// ============================================================
// K3: per-chunk kv = k^T @ (v*gexp)  (128x128), ksum = sum_c k*gexp
// 256 threads (16x16), 8x8 register tile.
// ============================================================
__global__ __launch_bounds__(256) void k_chunk_kv(
    const float* __restrict__ kin, const float* __restrict__ vin)
{
    __shared__ float sk[CS_][DH_];
    __shared__ float sv[CS_][DH_];
    __shared__ float sg[CS_];
    int chunk = blockIdx.x;
    int bh = chunk >> 7, n = chunk & 127;
    int b = bh >> 3, h = bh & 7;
    int tid = threadIdx.x;

    if (tid < 16) sg[tid] = g_gexp[bh*S_ + n*16 + tid];
    __syncthreads();
    for (int r = tid; r < CS_*DH_; r += 256) {
        int c = r >> 7, d = r & 127;
        size_t gidx = (size_t)(b*S_ + n*16 + c)*DIM_ + h*DH_ + d;
        sk[c][d] = kin[gidx];
        sv[c][d] = vin[gidx] * sg[c];
    }
    __syncthreads();

    int ty = tid >> 4, tx = tid & 15;
    float acc[8][8];
#pragma unroll
    for (int i = 0; i < 8; i++)
#pragma unroll
        for (int j = 0; j < 8; j++) acc[i][j] = 0.f;

#pragma unroll
    for (int c = 0; c < 16; c++) {
        float kk[8], vv[8];
#pragma unroll
        for (int i = 0; i < 8; i++) kk[i] = sk[c][ty + 16*i];
#pragma unroll
        for (int j = 0; j < 8; j++) vv[j] = sv[c][tx + 16*j];
#pragma unroll
        for (int i = 0; i < 8; i++)
#pragma unroll
            for (int j = 0; j < 8; j++)
                acc[i][j] = fmaf(kk[i], vv[j], acc[i][j]);
    }
    size_t obase = (size_t)chunk * DH_ * DH_;
#pragma unroll
    for (int i = 0; i < 8; i++)
#pragma unroll
        for (int j = 0; j < 8; j++)
            g_kv[obase + (size_t)(ty + 16*i)*DH_ + tx + 16*j] = acc[i][j];

    if (tid < DH_) {
        float s = 0.f;
#pragma unroll
        for (int c = 0; c < 16; c++) s = fmaf(sk[c][tid], sg[c], s);
        g_ksum[chunk*DH_ + tid] = s;
    }
}

// ============================================================
// K4a: scalar scan: m-sequence, a/b coefficients, mp. 32 threads.
// ============================================================
__global__ void k_scan_scalars(float* __restrict__ ml_out)
{
    int bh = threadIdx.x;
    if (bh >= BH_) return;
    float m = 0.f;
    for (int n = 0; n < NS_; n++) {
        int idx = bh*NS_ + n;
        float lfl = g_lfl[idx], mloc = g_mloc[idx];
        float mnew = fmaxf(lfl + m, mloc);
        g_a[idx]  = expf(lfl + m - mnew);
        g_b[idx]  = expf(mloc - mnew);
        g_mp[idx] = m;
        m = mnew;
    }
    ml_out[bh] = m;
}

// ============================================================
// K4b: element-parallel C scan (in-place kv -> Cp), outputs Cl.
// grid (64, 32) x 256 threads; each thread scans one C element.
// ============================================================
__global__ __launch_bounds__(256) void k_scan_C(float* __restrict__ Cl_out)
{
    __shared__ float sa[NS_], sb[NS_];
    int bh   = blockIdx.y;
    int elem = blockIdx.x * 256 + threadIdx.x;   // d*128+e
    if (threadIdx.x < NS_) {
        sa[threadIdx.x] = g_a[bh*NS_ + threadIdx.x];
        sb[threadIdx.x] = g_b[bh*NS_ + threadIdx.x];
    }
    __syncthreads();
    float C = 0.f;
    size_t base = (size_t)bh * NS_ * 16384 + elem;
    for (int n = 0; n < NS_; n++) {
        size_t idx = base + (size_t)n * 16384;
        float kvv = g_kv[idx];
        g_kv[idx] = C;                 // Cp[n] = pre-state
        C = fmaf(C, sa[n], kvv * sb[n]);
    }
    Cl_out[bh*16384 + elem] = C;
}

// ============================================================
// K4c: n-vector scan (in-place ksum -> np), outputs nl.
// ============================================================
__global__ __launch_bounds__(128) void k_scan_n(float* __restrict__ nl_out)
{
    __shared__ float sa[NS_], sb[NS_];
    int bh = blockIdx.x;
    int d  = threadIdx.x;
    sa[d] = g_a[bh*NS_ + d];
    sb[d] = g_b[bh*NS_ + d];
    __syncthreads();
    float nn = 0.f;
    for (int n = 0; n < NS_; n++) {
        size_t idx = (size_t)(bh*NS_ + n)*DH_ + d;
        float val = g_ksum[idx];
        g_ksum[idx] = nn;              // np[n] = pre-state
        nn = fmaf(nn, sa[n], val * sb[n]);
    }
    nl_out[bh*DH_ + d] = nn;
}

// ============================================================
// K5: intra-chunk attention + inter via Cp, fused output matmul
// h[c,e] = sum_{r<16} (E/norm)[c,r]*v[r,e] + sum_d (qd/norm)[c,d]*Cp[d,e]
// then per-(c) layernorm over e. 128 threads; 4x4 register tile.
// ============================================================
#define PAD 129
__global__ __launch_bounds__(128) void k_intra(
    const float* __restrict__ qin, const float* __restrict__ kin,
    const float* __restrict__ vin, const float* __restrict__ lnw,
    const float* __restrict__ lnb, float* __restrict__ out)
{
    __shared__ float sq [CS_][PAD];
    __shared__ float sk [CS_][PAD];
    __shared__ float sv [CS_][PAD];
    __shared__ float scp[CS_][PAD];
    __shared__ float sA [CS_][144];
    __shared__ float snp[DH_];
    __shared__ float slf[CS_], sig[CS_], sqn[CS_];
    __shared__ float smp;

    int chunk = blockIdx.x;
    int bh = chunk >> 7, n = chunk & 127;
    int b = bh >> 3, h = bh & 7;
    int tid = threadIdx.x;
    const float scale = 0.08838834764831845f; // 1/sqrt(128)

    for (int r = tid; r < CS_*DH_; r += 128) {
        int c = r >> 7, d = r & 127;
        size_t gidx = (size_t)(b*S_ + n*16 + c)*DIM_ + h*DH_ + d;
        sq[c][d] = qin[gidx] * scale;
        sk[c][d] = kin[gidx];
        sv[c][d] = vin[gidx];
    }
    if (tid < 16) {
        slf[tid] = g_lfacc[bh*S_ + n*16 + tid];
        sig[tid] = g_ig  [bh*S_ + n*16 + tid];
    }
    if (tid < DH_) snp[tid] = g_ksum[chunk*DH_ + tid];   // np
    if (tid == 0)  smp = g_mp[chunk];
    __syncthreads();

    // -------- Phase A: E matrix, norms --------
    {
        int c  = tid >> 3;       // 0..15
        int jj = tid & 7;        // handles j0=2jj, j1=2jj+1
        int j0 = 2*jj, j1 = 2*jj + 1;
        float qk0 = 0.f, qk1 = 0.f;
#pragma unroll 4
        for (int d = 0; d < DH_; d++) {
            float qv = sq[c][d];
            qk0 = fmaf(qv, sk[j0][d], qk0);
            qk1 = fmaf(qv, sk[j1][d], qk1);
        }
        float mp  = smp;
        float lD0 = ((j0 > c) ? NEG_ : (slf[c] - slf[j0])) + sig[j0];
        float lD1 = ((j1 > c) ? NEG_ : (slf[c] - slf[j1])) + sig[j1];
        float mrow = fmaxf(lD0, lD1);
#pragma unroll
        for (int off = 4; off; off >>= 1)
            mrow = fmaxf(mrow, __shfl_xor_sync(0xffffffffu, mrow, off, 8));
        float stab  = fmaxf(mrow, mp + slf[c]);
        float decay = expf(mp + slf[c] - stab);
        float E0 = qk0 * expf(lD0 - stab);
        float E1 = qk1 * expf(lD1 - stab);
        float Esum = E0 + E1;
#pragma unroll
        for (int off = 4; off; off >>= 1)
            Esum += __shfl_xor_sync(0xffffffffu, Esum, off, 8);
        float pn = 0.f;
#pragma unroll
        for (int t = 0; t < 16; t++) {
            int d = jj + 8*t;
            pn = fmaf(sq[c][d], snp[d], pn);
        }
#pragma unroll
        for (int off = 4; off; off >>= 1)
            pn += __shfl_xor_sync(0xffffffffu, pn, off, 8);
        float inter_n = decay * pn;
        float norm = fmaxf(fabsf(Esum + inter_n), expf(-stab)) + EPS_;
        float inv  = 1.f / norm;
        sA[c][j0] = E0 * inv;
        sA[c][j1] = E1 * inv;
        if (jj == 0) sqn[c] = decay * inv;
    }
    __syncthreads();

    // fill A columns 16..143 with (decay/norm)*q
    for (int r = tid; r < CS_*DH_; r += 128) {
        int c = r >> 7, d = r & 127;
        sA[c][16 + d] = sqn[c] * sq[c][d];
    }
    __syncthreads();

    // -------- Phase C: h = A(16x144) @ Bmat(144x128) --------
    int ty = tid >> 5, tx = tid & 31;   // c = ty+4k, e = tx+32j
    float acc[4][4];
#pragma unroll
    for (int kk = 0; kk < 4; kk++)
#pragma unroll
        for (int j = 0; j < 4; j++) acc[kk][j] = 0.f;

#pragma unroll
    for (int r = 0; r < 16; r++) {      // v rows
        float bj[4];
#pragma unroll
        for (int j = 0; j < 4; j++) bj[j] = sv[r][tx + 32*j];
#pragma unroll
        for (int kk = 0; kk < 4; kk++) {
            float a = sA[ty + 4*kk][r];
#pragma unroll
            for (int j = 0; j < 4; j++) acc[kk][j] = fmaf(a, bj[j], acc[kk][j]);
        }
    }
    size_t cpbase = (size_t)chunk * 16384;
    for (int dt = 0; dt < 8; dt++) {    // Cp rows, tiled 16 at a time
        __syncthreads();
        for (int r2 = tid; r2 < CS_*DH_; r2 += 128) {
            int dd = r2 >> 7, e = r2 & 127;
            scp[dd][e] = g_kv[cpbase + (size_t)(dt*16 + dd)*DH_ + e];
        }
        __syncthreads();
#pragma unroll
        for (int dd = 0; dd < 16; dd++) {
            int rr = 16 + dt*16 + dd;
            float bj[4];
#pragma unroll
            for (int j = 0; j < 4; j++) bj[j] = scp[dd][tx + 32*j];
#pragma unroll
            for (int kk = 0; kk < 4; kk++) {
                float a = sA[ty + 4*kk][rr];
#pragma unroll
                for (int j = 0; j < 4; j++) acc[kk][j] = fmaf(a, bj[j], acc[kk][j]);
            }
        }
    }

    // -------- Epilogue: per-row layernorm + store --------
#pragma unroll
    for (int kk = 0; kk < 4; kk++) {
        int c = ty + 4*kk;
        float s1 = 0.f;
#pragma unroll
        for (int j = 0; j < 4; j++) s1 += acc[kk][j];
#pragma unroll
        for (int off = 16; off; off >>= 1)
            s1 += __shfl_xor_sync(0xffffffffu, s1, off);
        float mu = s1 * (1.f/128.f);
        float s2 = 0.f;
#pragma unroll
        for (int j = 0; j < 4; j++) {
            float dlt = acc[kk][j] - mu;
            s2 += dlt * dlt;
        }
#pragma unroll
        for (int off = 16; off; off >>= 1)
            s2 += __shfl_xor_sync(0xffffffffu, s2, off);
        float rstd = rsqrtf(s2 * (1.f/128.f) + LN_EPS_);
        size_t ob = (size_t)(b*S_ + n*16 + c)*DIM_ + h*DH_;
#pragma unroll
        for (int j = 0; j < 4; j++) {
            int e = tx + 32*j;
            float wv = lnw[h*DH_ + e];
            float bv = lnb[h*DH_ + e];
            out[ob + e] = (acc[kk][j] - mu) * rstd * (1.f + wv) + bv;
        }
    }
}

// ============================================================
extern "C" void kernel_launch(void* const* d_in, const int* in_sizes, int n_in,
                              void* d_out, int out_size)
{
    const float* q   = (const float*)d_in[0];
    const float* k   = (const float*)d_in[1];
    const float* v   = (const float*)d_in[2];
    const float* Wi  = (const float*)d_in[3];
    const float* bi  = (const float*)d_in[4];
    const float* Wf  = (const float*)d_in[5];
    const float* bf  = (const float*)d_in[6];
    const float* lnw = (const float*)d_in[7];
    const float* lnb = (const float*)d_in[8];

    float* out = (float*)d_out;
    float* Cl  = out + (size_t)B_*S_*DIM_;       // 8388608
    float* nl  = Cl  + (size_t)BH_*DH_*DH_;      // +524288
    float* ml  = nl  + (size_t)BH_*DH_;          // +4096

    k_gates       <<< (B_*S_)/K1_T, 256 >>>(q, k, v, Wi, bi, Wf, bf);
    k_chunkprep   <<< NCHUNK/4, 128 >>>();
    k_scan_scalars<<< 1, 32 >>>(ml);
    k_chunk_kv    <<< NCHUNK, 256 >>>(k, v);
    dim3 g4b(64, BH_);
    k_scan_C      <<< g4b, 256 >>>(Cl);
    k_scan_n      <<< BH_, 128 >>>(nl);
    k_intra       <<< NCHUNK, 128 >>>(q, k, v, lnw, lnb, out);
}

// round 2
// speedup vs baseline: 1.5946x; 1.5946x over previous
#include <cuda_runtime.h>
#include <math.h>

// ---------------- problem constants ----------------
#define B_    4
#define S_    2048
#define DIM_  1024
#define NH_   8
#define DH_   128
#define CS_   16
#define NS_   128
#define BH_   (B_*NH_)        // 32
#define NCHUNK (BH_*NS_)      // 4096
#define ET_   32              // e-tile width in fused kernel
#define EPS_    1e-6f
#define LN_EPS_ 1e-5f
#define NEG_   -1e30f

// ---------------- scratch (device globals; no allocation) ----------------
__device__ float g_ig   [BH_*S_];
__device__ float g_fg   [BH_*S_];
__device__ float g_lfacc[BH_*S_];
__device__ float g_gexp [BH_*S_];
__device__ float g_lfl  [NCHUNK];
__device__ float g_mloc [NCHUNK];
__device__ float g_mp   [NCHUNK];
__device__ float g_a    [NCHUNK];
__device__ float g_b    [NCHUNK];
__device__ float g_ksum [NCHUNK*DH_];   // ksum, then np in-place after scan
__device__ float g_E    [NCHUNK*CS_*CS_]; // E/norm per chunk (16x16)
__device__ float g_qs   [NCHUNK*CS_];     // scale*decay/norm per (chunk,c)

// ============================================================
// K1: gates.  ig/fg[b,h,s] = <[q|k|v](b,s,:), W[h,:]> + bias
// ============================================================
#define K1_T 8
__global__ __launch_bounds__(256) void k_gates(
    const float* __restrict__ q, const float* __restrict__ k,
    const float* __restrict__ v, const float* __restrict__ Wi,
    const float* __restrict__ bi, const float* __restrict__ Wf,
    const float* __restrict__ bf)
{
    __shared__ float sg[K1_T][1024];
    int tid  = threadIdx.x;
    int base = blockIdx.x * K1_T;            // flattened (b*S + s)
    int w    = tid >> 5;                     // head
    int lane = tid & 31;
    const float* wi = Wi + w*3072;
    const float* wf = Wf + w*3072;

    float acc_i[K1_T], acc_f[K1_T];
#pragma unroll
    for (int t = 0; t < K1_T; t++) { acc_i[t] = 0.f; acc_f[t] = 0.f; }

    for (int seg = 0; seg < 3; seg++) {
        const float* src = (seg == 0) ? q : (seg == 1) ? k : v;
        for (int r = tid; r < K1_T*256; r += 256) {
            int t = r >> 8, d4 = r & 255;
            ((float4*)sg[t])[d4] =
                ((const float4*)(src + (size_t)(base + t)*1024))[d4];
        }
        __syncthreads();
        for (int kk = lane; kk < 1024; kk += 32) {
            float wiv = wi[seg*1024 + kk];
            float wfv = wf[seg*1024 + kk];
#pragma unroll
            for (int t = 0; t < K1_T; t++) {
                float g = sg[t][kk];
                acc_i[t] = fmaf(g, wiv, acc_i[t]);
                acc_f[t] = fmaf(g, wfv, acc_f[t]);
            }
        }
        __syncthreads();
    }
#pragma unroll
    for (int t = 0; t < K1_T; t++) {
#pragma unroll
        for (int off = 16; off; off >>= 1) {
            acc_i[t] += __shfl_xor_sync(0xffffffffu, acc_i[t], off);
            acc_f[t] += __shfl_xor_sync(0xffffffffu, acc_f[t], off);
        }
    }
    if (lane == 0) {
        float biv = bi[w], bfv = bf[w];
#pragma unroll
        for (int t = 0; t < K1_T; t++) {
            int bs = base + t;
            int b = bs >> 11, s = bs & 2047;
            int idx = (b*NH_ + w)*S_ + s;
            g_ig[idx] = acc_i[t] + biv;
            g_fg[idx] = acc_f[t] + bfv;
        }
    }
}

// ============================================================
// K2: per-chunk gate prep (warp 0) + ksum (128 threads).
// One block per chunk.
// ============================================================
__global__ __launch_bounds__(128) void k_chunkprep(const float* __restrict__ kin)
{
    __shared__ float sgexp[CS_];
    int chunk = blockIdx.x;
    int bh = chunk >> 7, n = chunk & 127;
    int b = bh >> 3, h = bh & 7;
    int tid = threadIdx.x;

    if (tid < 32) {
        int lane = tid;
        int c = lane & 15;
        int s = n*CS_ + c;
        float igv = 0.f, lf = 0.f;
        if (lane < 16) {
            float fgv = g_fg[bh*S_ + s];
            igv = g_ig[bh*S_ + s];
            lf  = fminf(fgv, 0.f) - log1pf(expf(-fabsf(fgv)));
        }
        float acc = lf;
#pragma unroll
        for (int off = 1; off < 16; off <<= 1) {
            float t = __shfl_up_sync(0xffffffffu, acc, off, 16);
            if (c >= off) acc += t;
        }
        float lfl = __shfl_sync(0xffffffffu, acc, 15, 16);
        float lg  = igv - acc + lfl;
        float m   = lg;
#pragma unroll
        for (int off = 8; off; off >>= 1)
            m = fmaxf(m, __shfl_xor_sync(0xffffffffu, m, off, 16));
        if (lane < 16) {
            float ge = expf(lg - m);
            g_lfacc[bh*S_ + s] = acc;
            g_gexp [bh*S_ + s] = ge;
            sgexp[c] = ge;
            if (lane == 0) { g_lfl[chunk] = lfl; g_mloc[chunk] = m; }
        }
    }
    __syncthreads();
    // ksum[d] = sum_c k[c][d]*gexp[c]
    int d = tid;
    float s = 0.f;
    size_t rb = (size_t)(b*S_ + n*16)*DIM_ + h*DH_ + d;
#pragma unroll
    for (int c = 0; c < 16; c++)
        s = fmaf(kin[rb + (size_t)c*DIM_], sgexp[c], s);
    g_ksum[chunk*DH_ + d] = s;
}

// ============================================================
// K3: scalar scan: a/b coefficients, mp, ml. 32 threads.
// ============================================================
__global__ void k_scan_scalars(float* __restrict__ ml_out)
{
    int bh = threadIdx.x;
    if (bh >= BH_) return;
    float m = 0.f;
    for (int n = 0; n < NS_; n++) {
        int idx = bh*NS_ + n;
        float lfl = g_lfl[idx], mloc = g_mloc[idx];
        float mnew = fmaxf(lfl + m, mloc);
        g_a[idx]  = expf(lfl + m - mnew);
        g_b[idx]  = expf(mloc - mnew);
        g_mp[idx] = m;
        m = mnew;
    }
    ml_out[bh] = m;
}

// ============================================================
// K4: n-vector scan (in-place ksum -> np), outputs nl.
// ============================================================
__global__ __launch_bounds__(128) void k_scan_n(float* __restrict__ nl_out)
{
    __shared__ float sa[NS_], sb[NS_];
    int bh = blockIdx.x;
    int d  = threadIdx.x;
    sa[d] = g_a[bh*NS_ + d];
    sb[d] = g_b[bh*NS_ + d];
    __syncthreads();
    float nn = 0.f;
    for (int n = 0; n < NS_; n++) {
        size_t idx = (size_t)(bh*NS_ + n)*DH_ + d;
        float val = g_ksum[idx];
        g_ksum[idx] = nn;              // np[n] = pre-state
        nn = fmaf(nn, sa[n], val * sb[n]);
    }
    nl_out[bh*DH_ + d] = nn;
}

// ============================================================
// K5: Phase A per chunk: E/norm matrix (16x16) + qscale vector.
// 128 threads per block, one block per chunk.
// ============================================================
#define PAD 129
__global__ __launch_bounds__(128) void k_phaseA(
    const float* __restrict__ qin, const float* __restrict__ kin)
{
    __shared__ float sq [CS_][PAD];
    __shared__ float sk [CS_][PAD];
    __shared__ float snp[DH_];
    __shared__ float slf[CS_], sig[CS_];
    __shared__ float smp;

    int chunk = blockIdx.x;
    int bh = chunk >> 7, n = chunk & 127;
    int b = bh >> 3, h = bh & 7;
    int tid = threadIdx.x;
    const float scale = 0.08838834764831845f; // 1/sqrt(128)

    for (int r = tid; r < CS_*DH_; r += 128) {
        int c = r >> 7, d = r & 127;
        size_t gidx = (size_t)(b*S_ + n*16 + c)*DIM_ + h*DH_ + d;
        sq[c][d] = qin[gidx] * scale;
        sk[c][d] = kin[gidx];
    }
    if (tid < 16) {
        slf[tid] = g_lfacc[bh*S_ + n*16 + tid];
        sig[tid] = g_ig  [bh*S_ + n*16 + tid];
    }
    snp[tid] = g_ksum[chunk*DH_ + tid];   // np (post scan)
    if (tid == 0) smp = g_mp[chunk];
    __syncthreads();

    int c  = tid >> 3;       // 0..15
    int jj = tid & 7;
    int j0 = 2*jj, j1 = 2*jj + 1;
    float qk0 = 0.f, qk1 = 0.f;
#pragma unroll 4
    for (int d = 0; d < DH_; d++) {
        float qv = sq[c][d];
        qk0 = fmaf(qv, sk[j0][d], qk0);
        qk1 = fmaf(qv, sk[j1][d], qk1);
    }
    float mp  = smp;
    float lD0 = ((j0 > c) ? NEG_ : (slf[c] - slf[j0])) + sig[j0];
    float lD1 = ((j1 > c) ? NEG_ : (slf[c] - slf[j1])) + sig[j1];
    float mrow = fmaxf(lD0, lD1);
#pragma unroll
    for (int off = 4; off; off >>= 1)
        mrow = fmaxf(mrow, __shfl_xor_sync(0xffffffffu, mrow, off, 8));
    float stab  = fmaxf(mrow, mp + slf[c]);
    float decay = expf(mp + slf[c] - stab);
    float E0 = qk0 * expf(lD0 - stab);
    float E1 = qk1 * expf(lD1 - stab);
    float Esum = E0 + E1;
#pragma unroll
    for (int off = 4; off; off >>= 1)
        Esum += __shfl_xor_sync(0xffffffffu, Esum, off, 8);
    float pn = 0.f;
#pragma unroll
    for (int t = 0; t < 16; t++) {
        int d = jj + 8*t;
        pn = fmaf(sq[c][d], snp[d], pn);
    }
#pragma unroll
    for (int off = 4; off; off >>= 1)
        pn += __shfl_xor_sync(0xffffffffu, pn, off, 8);
    float inter_n = decay * pn;
    float norm = fmaxf(fabsf(Esum + inter_n), expf(-stab)) + EPS_;
    float inv  = 1.f / norm;
    g_E[chunk*256 + c*16 + j0] = E0 * inv;
    g_E[chunk*256 + c*16 + j1] = E1 * inv;
    if (jj == 0) g_qs[chunk*16 + c] = decay * inv * scale;
}

// ============================================================
// K6: fused scan + output. One block per (e-tile, bh); 128 blocks.
// Holds C[128][ET] slice; per chunk: h = qs*(q@Cp) + (E/n)@v,
// then C = a*C + b*k^T(v*gexp).  q/k/v + constants register-prefetched.
// ============================================================
__global__ __launch_bounds__(256) void k_fused(
    const float* __restrict__ qin, const float* __restrict__ kin,
    const float* __restrict__ vin, float* __restrict__ out,
    float* __restrict__ Cl)
{
    __shared__ float sC[DH_][33];
    __shared__ float sq[CS_][132];
    __shared__ float sk[CS_][132];
    __shared__ float sv[CS_][34];
    __shared__ float sE[CS_][17];
    __shared__ float sg[CS_];
    __shared__ float sqs[CS_];
    __shared__ float sab[2];

    int et = blockIdx.x;      // 0..3
    int bh = blockIdx.y;      // 0..31
    int b = bh >> 3, h = bh & 7;
    int tid = threadIdx.x;

    // zero sC
    for (int i = tid; i < DH_*33; i += 256) (&sC[0][0])[i] = 0.f;

    float Cr[8][2];
#pragma unroll
    for (int dd = 0; dd < 8; dd++) { Cr[dd][0] = 0.f; Cr[dd][1] = 0.f; }

    int lc = tid >> 5;        // 0..7
    int lx = tid & 31;        // float4 col
    int vc = tid >> 4;        // 0..15
    int ve = tid & 15;        // float2 col
    int ty = tid >> 4;        // c row (inter) / d group (update)
    int tx = tid & 15;        // e col

    size_t rowbase0 = (size_t)(b*S_)*DIM_ + h*DH_;

    float4 qr[2], kr[2];
    float2 vr;
    float cE, cg = 0.f, cqs = 0.f, cab = 0.f;

    // ---- prefetch chunk 0 ----
    {
        int n = 0, chunk = bh*NS_;
#pragma unroll
        for (int i = 0; i < 2; i++) {
            int c = lc + 8*i;
            const float4* qp = (const float4*)(qin + rowbase0 + (size_t)(n*16 + c)*DIM_);
            const float4* kp = (const float4*)(kin + rowbase0 + (size_t)(n*16 + c)*DIM_);
            qr[i] = qp[lx]; kr[i] = kp[lx];
        }
        vr = ((const float2*)(vin + rowbase0 + (size_t)(n*16 + vc)*DIM_ + et*ET_))[ve];
        cE = g_E[chunk*256 + tid];
        if (tid < 16) { cg = g_gexp[bh*S_ + n*16 + tid]; cqs = g_qs[chunk*16 + tid]; }
        if (tid == 16) cab = g_a[chunk];
        if (tid == 17) cab = g_b[chunk];
    }

    for (int n = 0; n < NS_; n++) {
        // ---- stage current tiles into smem ----
#pragma unroll
        for (int i = 0; i < 2; i++) {
            int c = lc + 8*i;
            *(float4*)&sq[c][lx*4] = qr[i];
            *(float4*)&sk[c][lx*4] = kr[i];
        }
        *(float2*)&sv[vc][ve*2] = vr;
        sE[tid >> 4][tid & 15] = cE;
        if (tid < 16) { sg[tid] = cg; sqs[tid] = cqs; }
        if (tid == 16) sab[0] = cab;
        if (tid == 17) sab[1] = cab;
        __syncthreads();

        // ---- prefetch next chunk ----
        if (n + 1 < NS_) {
            int n2 = n + 1, chunk2 = bh*NS_ + n2;
#pragma unroll
            for (int i = 0; i < 2; i++) {
                int c = lc + 8*i;
                const float4* qp = (const float4*)(qin + rowbase0 + (size_t)(n2*16 + c)*DIM_);
                const float4* kp = (const float4*)(kin + rowbase0 + (size_t)(n2*16 + c)*DIM_);
                qr[i] = qp[lx]; kr[i] = kp[lx];
            }
            vr = ((const float2*)(vin + rowbase0 + (size_t)(n2*16 + vc)*DIM_ + et*ET_))[ve];
            cE = g_E[chunk2*256 + tid];
            if (tid < 16) { cg = g_gexp[bh*S_ + n2*16 + tid]; cqs = g_qs[chunk2*16 + tid]; }
            if (tid == 16) cab = g_a[chunk2];
            if (tid == 17) cab = g_b[chunk2];
        }

        // ---- h = qs*(q @ Cp) + (E/norm) @ v ----
        {
            float h0 = 0.f, h1 = 0.f;
#pragma unroll 8
            for (int d = 0; d < DH_; d++) {
                float qv = sq[ty][d];
                h0 = fmaf(qv, sC[d][tx],      h0);
                h1 = fmaf(qv, sC[d][tx + 16], h1);
            }
            float qsv = sqs[ty];
            h0 *= qsv; h1 *= qsv;
#pragma unroll
            for (int r = 0; r < 16; r++) {
                float en = sE[ty][r];
                h0 = fmaf(en, sv[r][tx],      h0);
                h1 = fmaf(en, sv[r][tx + 16], h1);
            }
            size_t ob = rowbase0 + (size_t)(n*16 + ty)*DIM_ + et*ET_;
            out[ob + tx]      = h0;
            out[ob + tx + 16] = h1;
        }

        // ---- C update: Cr = a*Cr + b * k^T (v*gexp) ----
        {
            float acc[8][2];
#pragma unroll
            for (int dd = 0; dd < 8; dd++) { acc[dd][0] = 0.f; acc[dd][1] = 0.f; }
#pragma unroll
            for (int c = 0; c < 16; c++) {
                float gv = sg[c];
                float v0 = sv[c][tx] * gv, v1 = sv[c][tx + 16] * gv;
#pragma unroll
                for (int dd = 0; dd < 8; dd++) {
                    float kv = sk[c][ty + 16*dd];
                    acc[dd][0] = fmaf(kv, v0, acc[dd][0]);
                    acc[dd][1] = fmaf(kv, v1, acc[dd][1]);
                }
            }
            float a = sab[0], bb = sab[1];
#pragma unroll
            for (int dd = 0; dd < 8; dd++) {
                Cr[dd][0] = fmaf(Cr[dd][0], a, acc[dd][0] * bb);
                Cr[dd][1] = fmaf(Cr[dd][1], a, acc[dd][1] * bb);
            }
        }
        __syncthreads();
        // publish updated C for next chunk's inter
#pragma unroll
        for (int dd = 0; dd < 8; dd++) {
            sC[ty + 16*dd][tx]      = Cr[dd][0];
            sC[ty + 16*dd][tx + 16] = Cr[dd][1];
        }
    }

    // ---- final state -> Cl ----
    size_t clb = (size_t)bh * (DH_*DH_);
#pragma unroll
    for (int dd = 0; dd < 8; dd++) {
        Cl[clb + (size_t)(ty + 16*dd)*DH_ + et*ET_ + tx]      = Cr[dd][0];
        Cl[clb + (size_t)(ty + 16*dd)*DH_ + et*ET_ + tx + 16] = Cr[dd][1];
    }
}

// ============================================================
// K7: in-place layernorm over out, per (b,s,head) row of 128.
// ============================================================
__global__ __launch_bounds__(256) void k_ln(
    const float* __restrict__ lnw, const float* __restrict__ lnb,
    float* __restrict__ out)
{
    int r = blockIdx.x*8 + (threadIdx.x >> 5);   // row over B*S*NH
    int lane = threadIdx.x & 31;
    int bs = r >> 3, h = r & 7;
    float4* p = (float4*)(out + (size_t)bs*DIM_ + h*DH_);
    float4 x = p[lane];
    float s1 = x.x + x.y + x.z + x.w;
#pragma unroll
    for (int off = 16; off; off >>= 1)
        s1 += __shfl_xor_sync(0xffffffffu, s1, off);
    float mu = s1 * (1.f/128.f);
    float dx = x.x - mu, dy = x.y - mu, dz = x.z - mu, dw = x.w - mu;
    float s2 = dx*dx + dy*dy + dz*dz + dw*dw;
#pragma unroll
    for (int off = 16; off; off >>= 1)
        s2 += __shfl_xor_sync(0xffffffffu, s2, off);
    float rstd = rsqrtf(s2 * (1.f/128.f) + LN_EPS_);
    float4 w = ((const float4*)(lnw + h*DH_))[lane];
    float4 bb = ((const float4*)(lnb + h*DH_))[lane];
    x.x = dx*rstd*(1.f + w.x) + bb.x;
    x.y = dy*rstd*(1.f + w.y) + bb.y;
    x.z = dz*rstd*(1.f + w.z) + bb.z;
    x.w = dw*rstd*(1.f + w.w) + bb.w;
    p[lane] = x;
}

// ============================================================
extern "C" void kernel_launch(void* const* d_in, const int* in_sizes, int n_in,
                              void* d_out, int out_size)
{
    const float* q   = (const float*)d_in[0];
    const float* k   = (const float*)d_in[1];
    const float* v   = (const float*)d_in[2];
    const float* Wi  = (const float*)d_in[3];
    const float* bi  = (const float*)d_in[4];
    const float* Wf  = (const float*)d_in[5];
    const float* bf  = (const float*)d_in[6];
    const float* lnw = (const float*)d_in[7];
    const float* lnb = (const float*)d_in[8];

    float* out = (float*)d_out;
    float* Cl  = out + (size_t)B_*S_*DIM_;       // 8388608
    float* nl  = Cl  + (size_t)BH_*DH_*DH_;      // +524288
    float* ml  = nl  + (size_t)BH_*DH_;          // +4096

    k_gates       <<< (B_*S_)/K1_T, 256 >>>(q, k, v, Wi, bi, Wf, bf);
    k_chunkprep   <<< NCHUNK, 128 >>>(k);
    k_scan_scalars<<< 1, 32 >>>(ml);
    k_scan_n      <<< BH_, 128 >>>(nl);
    k_phaseA      <<< NCHUNK, 128 >>>(q, k);
    dim3 gf(4, BH_);
    k_fused       <<< gf, 256 >>>(q, k, v, out, Cl);
    k_ln          <<< (B_*S_*NH_)/8, 256 >>>(lnw, lnb, out);
}

// round 3
// speedup vs baseline: 2.2395x; 1.4044x over previous
#include <cuda_runtime.h>
#include <math.h>

// ---------------- problem constants ----------------
#define B_    4
#define S_    2048
#define DIM_  1024
#define NH_   8
#define DH_   128
#define CS_   16
#define NS_   128
#define BH_   (B_*NH_)        // 32
#define NCHUNK (BH_*NS_)      // 4096
#define ET_   32              // e-tile width in fused kernel
#define EPS_    1e-6f
#define LN_EPS_ 1e-5f
#define NEG_   -1e30f

typedef unsigned long long ull;

// ---------------- f32x2 packed helpers (sm_103a) ----------------
__device__ __forceinline__ ull pk2(float lo, float hi) {
    ull r; asm("mov.b64 %0, {%1, %2};" : "=l"(r) : "f"(lo), "f"(hi)); return r;
}
__device__ __forceinline__ ull ffma2(ull a, ull b, ull c) {
    ull d; asm("fma.rn.f32x2 %0, %1, %2, %3;" : "=l"(d) : "l"(a), "l"(b), "l"(c)); return d;
}
__device__ __forceinline__ ull fmul2(ull a, ull b) {
    ull d; asm("mul.rn.f32x2 %0, %1, %2;" : "=l"(d) : "l"(a), "l"(b)); return d;
}
__device__ __forceinline__ void upk2(ull v, float& lo, float& hi) {
    asm("mov.b64 {%0, %1}, %2;" : "=f"(lo), "=f"(hi) : "l"(v));
}

// ---------------- scratch (device globals; no allocation) ----------------
__device__ float g_ig   [BH_*S_];
__device__ float g_fg   [BH_*S_];
__device__ float g_lfacc[BH_*S_];
__device__ float g_gexp [BH_*S_];
__device__ float g_lfl  [NCHUNK];
__device__ float g_mloc [NCHUNK];
__device__ float g_mp   [NCHUNK];
__device__ float g_a    [NCHUNK];
__device__ float g_b    [NCHUNK];
__device__ float g_ksum [NCHUNK*DH_];     // ksum, then np in-place after scan
__device__ float g_E    [NCHUNK*CS_*CS_]; // E/norm per chunk (16x16)
__device__ float g_qs   [NCHUNK*CS_];     // scale*decay/norm per (chunk,c)

// ============================================================
// K1: gates.  ig/fg[b,h,s] = <[q|k|v](b,s,:), W[h,:]> + bias
// ============================================================
#define K1_T 8
__global__ __launch_bounds__(256) void k_gates(
    const float* __restrict__ q, const float* __restrict__ k,
    const float* __restrict__ v, const float* __restrict__ Wi,
    const float* __restrict__ bi, const float* __restrict__ Wf,
    const float* __restrict__ bf)
{
    __shared__ float sg[K1_T][1024];
    int tid  = threadIdx.x;
    int base = blockIdx.x * K1_T;            // flattened (b*S + s)
    int w    = tid >> 5;                     // head
    int lane = tid & 31;
    const float* wi = Wi + w*3072;
    const float* wf = Wf + w*3072;

    float acc_i[K1_T], acc_f[K1_T];
#pragma unroll
    for (int t = 0; t < K1_T; t++) { acc_i[t] = 0.f; acc_f[t] = 0.f; }

    for (int seg = 0; seg < 3; seg++) {
        const float* src = (seg == 0) ? q : (seg == 1) ? k : v;
        for (int r = tid; r < K1_T*256; r += 256) {
            int t = r >> 8, d4 = r & 255;
            ((float4*)sg[t])[d4] =
                ((const float4*)(src + (size_t)(base + t)*1024))[d4];
        }
        __syncthreads();
        for (int kk = lane; kk < 1024; kk += 32) {
            float wiv = wi[seg*1024 + kk];
            float wfv = wf[seg*1024 + kk];
#pragma unroll
            for (int t = 0; t < K1_T; t++) {
                float g = sg[t][kk];
                acc_i[t] = fmaf(g, wiv, acc_i[t]);
                acc_f[t] = fmaf(g, wfv, acc_f[t]);
            }
        }
        __syncthreads();
    }
#pragma unroll
    for (int t = 0; t < K1_T; t++) {
#pragma unroll
        for (int off = 16; off; off >>= 1) {
            acc_i[t] += __shfl_xor_sync(0xffffffffu, acc_i[t], off);
            acc_f[t] += __shfl_xor_sync(0xffffffffu, acc_f[t], off);
        }
    }
    if (lane == 0) {
        float biv = bi[w], bfv = bf[w];
#pragma unroll
        for (int t = 0; t < K1_T; t++) {
            int bs = base + t;
            int b = bs >> 11, s = bs & 2047;
            int idx = (b*NH_ + w)*S_ + s;
            g_ig[idx] = acc_i[t] + biv;
            g_fg[idx] = acc_f[t] + bfv;
        }
    }
}

// ============================================================
// K2: per-chunk gate prep (warp 0) + ksum (128 threads).
// ============================================================
__global__ __launch_bounds__(128) void k_chunkprep(const float* __restrict__ kin)
{
    __shared__ float sgexp[CS_];
    int chunk = blockIdx.x;
    int bh = chunk >> 7, n = chunk & 127;
    int b = bh >> 3, h = bh & 7;
    int tid = threadIdx.x;

    if (tid < 32) {
        int lane = tid;
        int c = lane & 15;
        int s = n*CS_ + c;
        float igv = 0.f, lf = 0.f;
        if (lane < 16) {
            float fgv = g_fg[bh*S_ + s];
            igv = g_ig[bh*S_ + s];
            lf  = fminf(fgv, 0.f) - log1pf(expf(-fabsf(fgv)));
        }
        float acc = lf;
#pragma unroll
        for (int off = 1; off < 16; off <<= 1) {
            float t = __shfl_up_sync(0xffffffffu, acc, off, 16);
            if (c >= off) acc += t;
        }
        float lfl = __shfl_sync(0xffffffffu, acc, 15, 16);
        float lg  = igv - acc + lfl;
        float m   = lg;
#pragma unroll
        for (int off = 8; off; off >>= 1)
            m = fmaxf(m, __shfl_xor_sync(0xffffffffu, m, off, 16));
        if (lane < 16) {
            float ge = expf(lg - m);
            g_lfacc[bh*S_ + s] = acc;
            g_gexp [bh*S_ + s] = ge;
            sgexp[c] = ge;
            if (lane == 0) { g_lfl[chunk] = lfl; g_mloc[chunk] = m; }
        }
    }
    __syncthreads();
    int d = tid;
    float s = 0.f;
    size_t rb = (size_t)(b*S_ + n*16)*DIM_ + h*DH_ + d;
#pragma unroll
    for (int c = 0; c < 16; c++)
        s = fmaf(kin[rb + (size_t)c*DIM_], sgexp[c], s);
    g_ksum[chunk*DH_ + d] = s;
}

// ============================================================
// K3: scalar scan: a/b coefficients, mp, ml. 32 threads.
// ============================================================
__global__ void k_scan_scalars(float* __restrict__ ml_out)
{
    int bh = threadIdx.x;
    if (bh >= BH_) return;
    float m = 0.f;
    for (int n = 0; n < NS_; n++) {
        int idx = bh*NS_ + n;
        float lfl = g_lfl[idx], mloc = g_mloc[idx];
        float mnew = fmaxf(lfl + m, mloc);
        g_a[idx]  = expf(lfl + m - mnew);
        g_b[idx]  = expf(mloc - mnew);
        g_mp[idx] = m;
        m = mnew;
    }
    ml_out[bh] = m;
}

// ============================================================
// K4: n-vector scan (in-place ksum -> np), outputs nl.
// ============================================================
__global__ __launch_bounds__(128) void k_scan_n(float* __restrict__ nl_out)
{
    __shared__ float sa[NS_], sb[NS_];
    int bh = blockIdx.x;
    int d  = threadIdx.x;
    sa[d] = g_a[bh*NS_ + d];
    sb[d] = g_b[bh*NS_ + d];
    __syncthreads();
    float nn = 0.f;
    for (int n = 0; n < NS_; n++) {
        size_t idx = (size_t)(bh*NS_ + n)*DH_ + d;
        float val = g_ksum[idx];
        g_ksum[idx] = nn;              // np[n] = pre-state
        nn = fmaf(nn, sa[n], val * sb[n]);
    }
    nl_out[bh*DH_ + d] = nn;
}

// ============================================================
// K5: Phase A per chunk: E/norm matrix (16x16) + qscale vector.
// ============================================================
#define PAD 129
__global__ __launch_bounds__(128) void k_phaseA(
    const float* __restrict__ qin, const float* __restrict__ kin)
{
    __shared__ float sq [CS_][PAD];
    __shared__ float sk [CS_][PAD];
    __shared__ float snp[DH_];
    __shared__ float slf[CS_], sig[CS_];
    __shared__ float smp;

    int chunk = blockIdx.x;
    int bh = chunk >> 7, n = chunk & 127;
    int b = bh >> 3, h = bh & 7;
    int tid = threadIdx.x;
    const float scale = 0.08838834764831845f; // 1/sqrt(128)

    for (int r = tid; r < CS_*DH_; r += 128) {
        int c = r >> 7, d = r & 127;
        size_t gidx = (size_t)(b*S_ + n*16 + c)*DIM_ + h*DH_ + d;
        sq[c][d] = qin[gidx] * scale;
        sk[c][d] = kin[gidx];
    }
    if (tid < 16) {
        slf[tid] = g_lfacc[bh*S_ + n*16 + tid];
        sig[tid] = g_ig  [bh*S_ + n*16 + tid];
    }
    snp[tid] = g_ksum[chunk*DH_ + tid];
    if (tid == 0) smp = g_mp[chunk];
    __syncthreads();

    int c  = tid >> 3;
    int jj = tid & 7;
    int j0 = 2*jj, j1 = 2*jj + 1;
    float qk0 = 0.f, qk1 = 0.f;
#pragma unroll 4
    for (int d = 0; d < DH_; d++) {
        float qv = sq[c][d];
        qk0 = fmaf(qv, sk[j0][d], qk0);
        qk1 = fmaf(qv, sk[j1][d], qk1);
    }
    float mp  = smp;
    float lD0 = ((j0 > c) ? NEG_ : (slf[c] - slf[j0])) + sig[j0];
    float lD1 = ((j1 > c) ? NEG_ : (slf[c] - slf[j1])) + sig[j1];
    float mrow = fmaxf(lD0, lD1);
#pragma unroll
    for (int off = 4; off; off >>= 1)
        mrow = fmaxf(mrow, __shfl_xor_sync(0xffffffffu, mrow, off, 8));
    float stab  = fmaxf(mrow, mp + slf[c]);
    float decay = expf(mp + slf[c] - stab);
    float E0 = qk0 * expf(lD0 - stab);
    float E1 = qk1 * expf(lD1 - stab);
    float Esum = E0 + E1;
#pragma unroll
    for (int off = 4; off; off >>= 1)
        Esum += __shfl_xor_sync(0xffffffffu, Esum, off, 8);
    float pn = 0.f;
#pragma unroll
    for (int t = 0; t < 16; t++) {
        int d = jj + 8*t;
        pn = fmaf(sq[c][d], snp[d], pn);
    }
#pragma unroll
    for (int off = 4; off; off >>= 1)
        pn += __shfl_xor_sync(0xffffffffu, pn, off, 8);
    float inter_n = decay * pn;
    float norm = fmaxf(fabsf(Esum + inter_n), expf(-stab)) + EPS_;
    float inv  = 1.f / norm;
    g_E[chunk*256 + c*16 + j0] = E0 * inv;
    g_E[chunk*256 + c*16 + j1] = E1 * inv;
    if (jj == 0) g_qs[chunk*16 + c] = decay * inv * scale;
}

// ============================================================
// K6: fused scan + output (v2): warp-specialized, f32x2 packed.
//  warps 0-3: inter  h = qs*(q@Cp) + (E/n)@v  (K-split + reduction)
//  warps 4-7: C state in registers; kv update; republish sC.
// ============================================================
__global__ __launch_bounds__(256, 1) void k_fused2(
    const float* __restrict__ qin, const float* __restrict__ kin,
    const float* __restrict__ vin, float* __restrict__ out,
    float* __restrict__ Cl)
{
    __shared__ float sq[CS_][132];
    __shared__ float sk[CS_][132];
    __shared__ float sv[CS_][36];
    __shared__ float sE[CS_][17];
    __shared__ float spart[4][CS_][36];
    __shared__ float sC[DH_][ET_];
    __shared__ float sg[CS_], sqs[CS_], sab[2];

    int et = blockIdx.x;      // 0..3
    int bh = blockIdx.y;      // 0..31
    int b = bh >> 3, h = bh & 7;
    int tid = threadIdx.x;
    int wid = tid >> 5;

    size_t rowbase = (size_t)(b*S_)*DIM_ + h*DH_;

    // zero sC
    for (int i = tid; i < DH_*ET_; i += 256) (&sC[0][0])[i] = 0.f;

    // staging thread map (all 256 threads)
    int c16 = tid >> 4, l16 = tid & 15;

    // update-warp state
    int utid = tid - 128;
    int uy = (utid >= 0) ? (utid >> 4) : 0;   // 0..7
    int ux = utid & 15;
    ull C2[4][4];
#pragma unroll
    for (int g = 0; g < 4; g++)
#pragma unroll
        for (int j = 0; j < 4; j++) C2[g][j] = 0ull;

    // prefetch registers
    float4 qr0, qr1, kr0, kr1;
    float2 vr;
    float cE, cg_ = 0.f, cqs = 0.f, cab = 0.f;

    {   // prefetch chunk 0
        int n = 0, chunk = bh*NS_;
        const float* qrow = qin + rowbase + (size_t)(n*16 + c16)*DIM_;
        const float* krow = kin + rowbase + (size_t)(n*16 + c16)*DIM_;
        qr0 = ((const float4*)qrow)[l16];
        qr1 = ((const float4*)qrow)[l16 + 16];
        kr0 = ((const float4*)krow)[l16];
        kr1 = ((const float4*)krow)[l16 + 16];
        vr  = ((const float2*)(vin + rowbase + (size_t)(n*16 + c16)*DIM_ + et*ET_))[l16];
        cE  = g_E[chunk*256 + tid];
        if (tid < 16) { cg_ = g_gexp[bh*S_ + n*16 + tid]; cqs = g_qs[chunk*16 + tid]; }
        if (tid == 16) cab = g_a[chunk];
        if (tid == 17) cab = g_b[chunk];
    }

    for (int n = 0; n < NS_; n++) {
        // ---- stage ----
        *(float4*)&sq[c16][l16*4]      = qr0;
        *(float4*)&sq[c16][64 + l16*4] = qr1;
        *(float4*)&sk[c16][l16*4]      = kr0;
        *(float4*)&sk[c16][64 + l16*4] = kr1;
        *(float2*)&sv[c16][l16*2]      = vr;
        sE[c16][l16] = cE;
        if (tid < 16) { sg[tid] = cg_; sqs[tid] = cqs; }
        if (tid == 16) sab[0] = cab;
        if (tid == 17) sab[1] = cab;
        __syncthreads();

        // ---- prefetch next ----
        if (n + 1 < NS_) {
            int n2 = n + 1, chunk2 = bh*NS_ + n2;
            const float* qrow = qin + rowbase + (size_t)(n2*16 + c16)*DIM_;
            const float* krow = kin + rowbase + (size_t)(n2*16 + c16)*DIM_;
            qr0 = ((const float4*)qrow)[l16];
            qr1 = ((const float4*)qrow)[l16 + 16];
            kr0 = ((const float4*)krow)[l16];
            kr1 = ((const float4*)krow)[l16 + 16];
            vr  = ((const float2*)(vin + rowbase + (size_t)(n2*16 + c16)*DIM_ + et*ET_))[l16];
            cE  = g_E[chunk2*256 + tid];
            if (tid < 16) { cg_ = g_gexp[bh*S_ + n2*16 + tid]; cqs = g_qs[chunk2*16 + tid]; }
            if (tid == 16) cab = g_a[chunk2];
            if (tid == 17) cab = g_b[chunk2];
        }

        if (wid < 4) {
            // ---- inter: K-split q@Cp + E-part ----
            int lane = tid & 31;
            int cgi = lane >> 3;        // c-group: c_i = cgi + 4i
            int eg  = lane & 7;         // e-quad
            ull acc[4][2];
#pragma unroll
            for (int i = 0; i < 4; i++) { acc[i][0] = 0ull; acc[i][1] = 0ull; }

            int k0 = wid * 32;
#pragma unroll 4
            for (int kk = 0; kk < 32; kk++) {
                int kr = k0 + kk;
                ull cA = *(const ull*)&sC[kr][eg*4];
                ull cB = *(const ull*)&sC[kr][eg*4 + 2];
#pragma unroll
                for (int i = 0; i < 4; i++) {
                    float qv = sq[cgi + 4*i][kr];
                    ull q2 = pk2(qv, qv);
                    acc[i][0] = ffma2(q2, cA, acc[i][0]);
                    acc[i][1] = ffma2(q2, cB, acc[i][1]);
                }
            }
            // scale the q@Cp part by qs
#pragma unroll
            for (int i = 0; i < 4; i++) {
                float qsv = sqs[cgi + 4*i];
                ull q2 = pk2(qsv, qsv);
                acc[i][0] = fmul2(acc[i][0], q2);
                acc[i][1] = fmul2(acc[i][1], q2);
            }
            // E-part: r in [4*wid, 4*wid+4)
#pragma unroll
            for (int rr = 0; rr < 4; rr++) {
                int r = wid*4 + rr;
                ull vA = *(const ull*)&sv[r][eg*4];
                ull vB = *(const ull*)&sv[r][eg*4 + 2];
#pragma unroll
                for (int i = 0; i < 4; i++) {
                    float ev = sE[cgi + 4*i][r];
                    ull e2 = pk2(ev, ev);
                    acc[i][0] = ffma2(e2, vA, acc[i][0]);
                    acc[i][1] = ffma2(e2, vB, acc[i][1]);
                }
            }
            // store partials
#pragma unroll
            for (int i = 0; i < 4; i++) {
                *(ull*)&spart[wid][cgi + 4*i][eg*4]     = acc[i][0];
                *(ull*)&spart[wid][cgi + 4*i][eg*4 + 2] = acc[i][1];
            }
        } else {
            // ---- update: acc = k^T (v*gexp); C = a*C + b*acc ----
            ull acc[4][4];
#pragma unroll
            for (int g = 0; g < 4; g++)
#pragma unroll
                for (int j = 0; j < 4; j++) acc[g][j] = 0ull;

#pragma unroll
            for (int c = 0; c < 16; c++) {
                float2 v2 = *(const float2*)&sv[c][ux*2];
                float gv = sg[c];
                ull vg = pk2(v2.x * gv, v2.y * gv);
#pragma unroll
                for (int g = 0; g < 4; g++) {
                    float4 k4 = *(const float4*)&sk[c][uy*16 + g*4];
                    acc[g][0] = ffma2(pk2(k4.x, k4.x), vg, acc[g][0]);
                    acc[g][1] = ffma2(pk2(k4.y, k4.y), vg, acc[g][1]);
                    acc[g][2] = ffma2(pk2(k4.z, k4.z), vg, acc[g][2]);
                    acc[g][3] = ffma2(pk2(k4.w, k4.w), vg, acc[g][3]);
                }
            }
            float av = sab[0], bv = sab[1];
            ull a2 = pk2(av, av), b2 = pk2(bv, bv);
#pragma unroll
            for (int g = 0; g < 4; g++)
#pragma unroll
                for (int j = 0; j < 4; j++)
                    C2[g][j] = ffma2(C2[g][j], a2, fmul2(acc[g][j], b2));
        }
        __syncthreads();

        if (wid < 4) {
            // ---- reduce partials + store h ----
            int c = tid >> 3, eq = tid & 7;
            float4 s0 = *(const float4*)&spart[0][c][eq*4];
            float4 s1 = *(const float4*)&spart[1][c][eq*4];
            float4 s2 = *(const float4*)&spart[2][c][eq*4];
            float4 s3 = *(const float4*)&spart[3][c][eq*4];
            float4 hv;
            hv.x = (s0.x + s1.x) + (s2.x + s3.x);
            hv.y = (s0.y + s1.y) + (s2.y + s3.y);
            hv.z = (s0.z + s1.z) + (s2.z + s3.z);
            hv.w = (s0.w + s1.w) + (s2.w + s3.w);
            *(float4*)(out + rowbase + (size_t)(n*16 + c)*DIM_ + et*ET_ + eq*4) = hv;
        } else {
            // ---- republish C for next chunk's inter ----
#pragma unroll
            for (int g = 0; g < 4; g++)
#pragma unroll
                for (int j = 0; j < 4; j++)
                    *(ull*)&sC[uy*16 + g*4 + j][ux*2] = C2[g][j];
        }
        // next loop-top __syncthreads() orders publish/stage vs reads
    }

    // ---- final state -> Cl ----
    if (wid >= 4) {
        size_t clb = (size_t)bh * (DH_*DH_);
#pragma unroll
        for (int g = 0; g < 4; g++)
#pragma unroll
            for (int j = 0; j < 4; j++) {
                float lo, hi;
                upk2(C2[g][j], lo, hi);
                size_t o = clb + (size_t)(uy*16 + g*4 + j)*DH_ + et*ET_ + ux*2;
                Cl[o]   = lo;
                Cl[o+1] = hi;
            }
    }
}

// ============================================================
// K7: in-place layernorm over out, per (b,s,head) row of 128.
// ============================================================
__global__ __launch_bounds__(256) void k_ln(
    const float* __restrict__ lnw, const float* __restrict__ lnb,
    float* __restrict__ out)
{
    int r = blockIdx.x*8 + (threadIdx.x >> 5);   // row over B*S*NH
    int lane = threadIdx.x & 31;
    int bs = r >> 3, h = r & 7;
    float4* p = (float4*)(out + (size_t)bs*DIM_ + h*DH_);
    float4 x = p[lane];
    float s1 = x.x + x.y + x.z + x.w;
#pragma unroll
    for (int off = 16; off; off >>= 1)
        s1 += __shfl_xor_sync(0xffffffffu, s1, off);
    float mu = s1 * (1.f/128.f);
    float dx = x.x - mu, dy = x.y - mu, dz = x.z - mu, dw = x.w - mu;
    float s2 = dx*dx + dy*dy + dz*dz + dw*dw;
#pragma unroll
    for (int off = 16; off; off >>= 1)
        s2 += __shfl_xor_sync(0xffffffffu, s2, off);
    float rstd = rsqrtf(s2 * (1.f/128.f) + LN_EPS_);
    float4 w = ((const float4*)(lnw + h*DH_))[lane];
    float4 bb = ((const float4*)(lnb + h*DH_))[lane];
    x.x = dx*rstd*(1.f + w.x) + bb.x;
    x.y = dy*rstd*(1.f + w.y) + bb.y;
    x.z = dz*rstd*(1.f + w.z) + bb.z;
    x.w = dw*rstd*(1.f + w.w) + bb.w;
    p[lane] = x;
}

// ============================================================
extern "C" void kernel_launch(void* const* d_in, const int* in_sizes, int n_in,
                              void* d_out, int out_size)
{
    const float* q   = (const float*)d_in[0];
    const float* k   = (const float*)d_in[1];
    const float* v   = (const float*)d_in[2];
    const float* Wi  = (const float*)d_in[3];
    const float* bi  = (const float*)d_in[4];
    const float* Wf  = (const float*)d_in[5];
    const float* bf  = (const float*)d_in[6];
    const float* lnw = (const float*)d_in[7];
    const float* lnb = (const float*)d_in[8];

    float* out = (float*)d_out;
    float* Cl  = out + (size_t)B_*S_*DIM_;       // 8388608
    float* nl  = Cl  + (size_t)BH_*DH_*DH_;      // +524288
    float* ml  = nl  + (size_t)BH_*DH_;          // +4096

    k_gates       <<< (B_*S_)/K1_T, 256 >>>(q, k, v, Wi, bi, Wf, bf);
    k_chunkprep   <<< NCHUNK, 128 >>>(k);
    k_scan_scalars<<< 1, 32 >>>(ml);
    k_scan_n      <<< BH_, 128 >>>(nl);
    k_phaseA      <<< NCHUNK, 128 >>>(q, k);
    dim3 gf(4, BH_);
    k_fused2      <<< gf, 256 >>>(q, k, v, out, Cl);
    k_ln          <<< (B_*S_*NH_)/8, 256 >>>(lnw, lnb, out);
}

// round 4
// speedup vs baseline: 2.3407x; 1.0452x over previous
#include <cuda_runtime.h>
#include <math.h>

// ---------------- problem constants ----------------
#define B_    4
#define S_    2048
#define DIM_  1024
#define NH_   8
#define DH_   128
#define CS_   16
#define NS_   128
#define BH_   (B_*NH_)        // 32
#define NCHUNK (BH_*NS_)      // 4096
#define ET_   32              // e-tile width in fused kernel
#define EPS_    1e-6f
#define LN_EPS_ 1e-5f
#define NEG_   -1e30f

typedef unsigned long long ull;

// ---------------- f32x2 packed helpers (sm_103a) ----------------
__device__ __forceinline__ ull pk2(float lo, float hi) {
    ull r; asm("mov.b64 %0, {%1, %2};" : "=l"(r) : "f"(lo), "f"(hi)); return r;
}
__device__ __forceinline__ ull ffma2(ull a, ull b, ull c) {
    ull d; asm("fma.rn.f32x2 %0, %1, %2, %3;" : "=l"(d) : "l"(a), "l"(b), "l"(c)); return d;
}
__device__ __forceinline__ ull fmul2(ull a, ull b) {
    ull d; asm("mul.rn.f32x2 %0, %1, %2;" : "=l"(d) : "l"(a), "l"(b)); return d;
}

// ---------------- scratch (device globals; no allocation) ----------------
__device__ float g_ig   [BH_*S_];
__device__ float g_fg   [BH_*S_];
__device__ float g_lfacc[BH_*S_];
__device__ float g_gexp [BH_*S_];
__device__ float g_mp   [NCHUNK];
__device__ float g_a    [NCHUNK];
__device__ float g_b    [NCHUNK];
__device__ float g_E    [NCHUNK*CS_*CS_]; // unnormalized E per chunk (16x16)
__device__ float g_qs   [NCHUNK*CS_];     // decay*scale per (chunk,c)
__device__ float g_esum [NCHUNK*CS_];     // row sums of E
__device__ float g_expns[NCHUNK*CS_];     // exp(-stab) per (chunk,c)

// ============================================================
// K1: gates.  ig/fg[b,h,s] = <[q|k|v](b,s,:), W[h,:]> + bias
// ============================================================
#define K1_T 8
__global__ __launch_bounds__(256) void k_gates(
    const float* __restrict__ q, const float* __restrict__ k,
    const float* __restrict__ v, const float* __restrict__ Wi,
    const float* __restrict__ bi, const float* __restrict__ Wf,
    const float* __restrict__ bf)
{
    __shared__ float sg[K1_T][1024];
    int tid  = threadIdx.x;
    int base = blockIdx.x * K1_T;            // flattened (b*S + s)
    int w    = tid >> 5;                     // head
    int lane = tid & 31;
    const float* wi = Wi + w*3072;
    const float* wf = Wf + w*3072;

    float acc_i[K1_T], acc_f[K1_T];
#pragma unroll
    for (int t = 0; t < K1_T; t++) { acc_i[t] = 0.f; acc_f[t] = 0.f; }

    for (int seg = 0; seg < 3; seg++) {
        const float* src = (seg == 0) ? q : (seg == 1) ? k : v;
        for (int r = tid; r < K1_T*256; r += 256) {
            int t = r >> 8, d4 = r & 255;
            ((float4*)sg[t])[d4] =
                ((const float4*)(src + (size_t)(base + t)*1024))[d4];
        }
        __syncthreads();
        const float* wis = wi + seg*1024;
        const float* wfs = wf + seg*1024;
#pragma unroll 2
        for (int kk = lane*4; kk < 1024; kk += 128) {
            float4 w4i = *(const float4*)&wis[kk];
            float4 w4f = *(const float4*)&wfs[kk];
#pragma unroll
            for (int t = 0; t < K1_T; t++) {
                float4 g4 = *(const float4*)&sg[t][kk];
                acc_i[t] = fmaf(g4.x, w4i.x, acc_i[t]);
                acc_i[t] = fmaf(g4.y, w4i.y, acc_i[t]);
                acc_i[t] = fmaf(g4.z, w4i.z, acc_i[t]);
                acc_i[t] = fmaf(g4.w, w4i.w, acc_i[t]);
                acc_f[t] = fmaf(g4.x, w4f.x, acc_f[t]);
                acc_f[t] = fmaf(g4.y, w4f.y, acc_f[t]);
                acc_f[t] = fmaf(g4.z, w4f.z, acc_f[t]);
                acc_f[t] = fmaf(g4.w, w4f.w, acc_f[t]);
            }
        }
        __syncthreads();
    }
#pragma unroll
    for (int t = 0; t < K1_T; t++) {
#pragma unroll
        for (int off = 16; off; off >>= 1) {
            acc_i[t] += __shfl_xor_sync(0xffffffffu, acc_i[t], off);
            acc_f[t] += __shfl_xor_sync(0xffffffffu, acc_f[t], off);
        }
    }
    if (lane == 0) {
        float biv = bi[w], bfv = bf[w];
#pragma unroll
        for (int t = 0; t < K1_T; t++) {
            int bs = base + t;
            int b = bs >> 11, s = bs & 2047;
            int idx = (b*NH_ + w)*S_ + s;
            g_ig[idx] = acc_i[t] + biv;
            g_fg[idx] = acc_f[t] + bfv;
        }
    }
}

// ============================================================
// K2: per-bh prep: logsigmoid cumsum, gexp, and the (a,b,mp)
// max-plus scan over 128 chunks. One block (128 thr) per bh;
// thread n owns chunk n.
// ============================================================
__global__ __launch_bounds__(128) void k_prep(float* __restrict__ ml_out)
{
    __shared__ float wLs[4], wMs[4];
    int bh = blockIdx.x;
    int n  = threadIdx.x;           // chunk
    int lane = n & 31, wid = n >> 5;
    int base = bh*S_ + n*16;

    float fg[16], ig[16];
#pragma unroll
    for (int i = 0; i < 4; i++) {
        float4 f4 = *(const float4*)&g_fg[base + i*4];
        float4 i4 = *(const float4*)&g_ig[base + i*4];
        fg[i*4+0]=f4.x; fg[i*4+1]=f4.y; fg[i*4+2]=f4.z; fg[i*4+3]=f4.w;
        ig[i*4+0]=i4.x; ig[i*4+1]=i4.y; ig[i*4+2]=i4.z; ig[i*4+3]=i4.w;
    }
    float lfacc[16];
    float acc = 0.f;
#pragma unroll
    for (int c = 0; c < 16; c++) {
        float f = fg[c];
        float lf = fminf(f, 0.f) - log1pf(expf(-fabsf(f)));
        acc += lf;
        lfacc[c] = acc;
    }
    float lfl = lfacc[15];
    float lg[16];
    float mloc = NEG_;
#pragma unroll
    for (int c = 0; c < 16; c++) {
        lg[c] = ig[c] - lfacc[c] + lfl;
        mloc = fmaxf(mloc, lg[c]);
    }
#pragma unroll
    for (int i = 0; i < 4; i++) {
        float4 a4, g4;
        a4.x=lfacc[i*4+0]; a4.y=lfacc[i*4+1]; a4.z=lfacc[i*4+2]; a4.w=lfacc[i*4+3];
        g4.x=expf(lg[i*4+0]-mloc); g4.y=expf(lg[i*4+1]-mloc);
        g4.z=expf(lg[i*4+2]-mloc); g4.w=expf(lg[i*4+3]-mloc);
        *(float4*)&g_lfacc[base + i*4] = a4;
        *(float4*)&g_gexp [base + i*4] = g4;
    }

    // max-plus scan over chunks: f(m) = max(m + L, M)
    float L = lfl, M = mloc;
#pragma unroll
    for (int off = 1; off < 32; off <<= 1) {
        float Lp = __shfl_up_sync(0xffffffffu, L, off);
        float Mp = __shfl_up_sync(0xffffffffu, M, off);
        if (lane >= off) { M = fmaxf(Mp + L, M); L = Lp + L; }
    }
    if (lane == 31) { wLs[wid] = L; wMs[wid] = M; }
    __syncthreads();
    float PL = 0.f, PM = NEG_;
#pragma unroll
    for (int ww = 0; ww < 4; ww++) {
        if (ww < wid) { PM = fmaxf(PM + wLs[ww], wMs[ww]); PL += wLs[ww]; }
    }
    // exclusive within warp
    float Lex_w = __shfl_up_sync(0xffffffffu, L, 1);
    float Mex_w = __shfl_up_sync(0xffffffffu, M, 1);
    if (lane == 0) { Lex_w = 0.f; Mex_w = NEG_; }
    float Lex = PL + Lex_w;
    float Mex = fmaxf(PM + Lex_w, Mex_w);
    float mp = fmaxf(Lex, Mex);               // m before chunk n (m0 = 0)
    float Linc = PL + L;
    float Minc = fmaxf(PM + L, M);
    float m = fmaxf(Linc, Minc);              // m after chunk n

    int idx = bh*NS_ + n;
    g_a [idx] = expf(lfl + mp - m);
    g_b [idx] = expf(mloc - m);
    g_mp[idx] = mp;
    if (n == NS_-1) ml_out[bh] = m;
}

// ============================================================
// K3: Phase A per chunk: unnormalized E (16x16), Esum, decay,
// exp(-stab). One block (128 thr) per chunk.
// ============================================================
#define PAD 129
__global__ __launch_bounds__(128) void k_phaseA(
    const float* __restrict__ qin, const float* __restrict__ kin)
{
    __shared__ float sq [CS_][PAD];
    __shared__ float sk [CS_][PAD];
    __shared__ float slf[CS_], sig[CS_];
    __shared__ float smp;

    int chunk = blockIdx.x;
    int bh = chunk >> 7, n = chunk & 127;
    int b = bh >> 3, h = bh & 7;
    int tid = threadIdx.x;
    const float scale = 0.08838834764831845f; // 1/sqrt(128)

    for (int r = tid; r < CS_*DH_; r += 128) {
        int c = r >> 7, d = r & 127;
        size_t gidx = (size_t)(b*S_ + n*16 + c)*DIM_ + h*DH_ + d;
        sq[c][d] = qin[gidx] * scale;
        sk[c][d] = kin[gidx];
    }
    if (tid < 16) {
        slf[tid] = g_lfacc[bh*S_ + n*16 + tid];
        sig[tid] = g_ig  [bh*S_ + n*16 + tid];
    }
    if (tid == 0) smp = g_mp[chunk];
    __syncthreads();

    int c  = tid >> 3;
    int jj = tid & 7;
    int j0 = 2*jj, j1 = 2*jj + 1;
    float qk0 = 0.f, qk1 = 0.f;
#pragma unroll 4
    for (int d = 0; d < DH_; d++) {
        float qv = sq[c][d];
        qk0 = fmaf(qv, sk[j0][d], qk0);
        qk1 = fmaf(qv, sk[j1][d], qk1);
    }
    float mp  = smp;
    float lD0 = ((j0 > c) ? NEG_ : (slf[c] - slf[j0])) + sig[j0];
    float lD1 = ((j1 > c) ? NEG_ : (slf[c] - slf[j1])) + sig[j1];
    float mrow = fmaxf(lD0, lD1);
#pragma unroll
    for (int off = 4; off; off >>= 1)
        mrow = fmaxf(mrow, __shfl_xor_sync(0xffffffffu, mrow, off, 8));
    float stab  = fmaxf(mrow, mp + slf[c]);
    float decay = expf(mp + slf[c] - stab);
    float E0 = qk0 * expf(lD0 - stab);
    float E1 = qk1 * expf(lD1 - stab);
    float Esum = E0 + E1;
#pragma unroll
    for (int off = 4; off; off >>= 1)
        Esum += __shfl_xor_sync(0xffffffffu, Esum, off, 8);
    g_E[chunk*256 + c*16 + j0] = E0;
    g_E[chunk*256 + c*16 + j1] = E1;
    if (jj == 0) {
        g_qs   [chunk*16 + c] = decay * scale;
        g_esum [chunk*16 + c] = Esum;
        g_expns[chunk*16 + c] = expf(-stab);
    }
}

// ============================================================
// K4: fused scan + output (v3): 512 threads, warp-specialized.
//  warps 0-7 : inter  hraw = qs*(q@Cp) + E_un@v  (K-split), pn partials
//  warps 8-15: C state in regs; kv update; n-state scan; republish sC
//  epilogue  : reduce partials, invnorm row scale, store h
// ============================================================
__global__ __launch_bounds__(512, 1) void k_fused3(
    const float* __restrict__ qin, const float* __restrict__ kin,
    const float* __restrict__ vin, float* __restrict__ out,
    float* __restrict__ Cl, float* __restrict__ nl)
{
    __shared__ float sq[CS_][132];
    __shared__ float sk[CS_][132];
    __shared__ float sv[CS_][36];
    __shared__ float sE[CS_][17];
    __shared__ float spart[8][CS_][36];
    __shared__ float spn[8][CS_];
    __shared__ float sC[DH_][ET_];
    __shared__ float sn[DH_];
    __shared__ float sg[CS_], sqs[CS_];

    int et = blockIdx.x;      // 0..3
    int bh = blockIdx.y;      // 0..31
    int b = bh >> 3, h = bh & 7;
    int tid = threadIdx.x;
    int wid = tid >> 5;
    int lane = tid & 31;

    size_t rowbase = (size_t)(b*S_)*DIM_ + h*DH_;

    // zero state
    for (int i = tid; i < DH_*ET_; i += 512) (&sC[0][0])[i] = 0.f;
    if (tid < DH_) sn[tid] = 0.f;

    // staging map
    int c16 = tid >> 5, l32 = tid & 31;

    // inter role
    int cgi = lane >> 3, eg = lane & 7;
    // update role
    int utid = tid - 256;
    int ux = utid & 15, uyy = (utid >= 0) ? (utid >> 4) : 0;

    float Cf[8][2];
#pragma unroll
    for (int g = 0; g < 8; g++) { Cf[g][0] = 0.f; Cf[g][1] = 0.f; }

    // prefetch regs
    float4 qr, kr;
    float2 vr = make_float2(0.f, 0.f);
    float cE = 0.f, cg_ = 0.f, cqs = 0.f;
    float nab_a = 0.f, nab_b = 0.f;          // update threads
    float nqs = 0.f, nes = 0.f, nxs = 0.f;   // reduce threads (tid<128)

    {   // prefetch chunk 0
        int n = 0, chunk = bh*NS_;
        const float* qrow = qin + rowbase + (size_t)(n*16 + c16)*DIM_;
        const float* krow = kin + rowbase + (size_t)(n*16 + c16)*DIM_;
        qr = ((const float4*)qrow)[l32];
        kr = ((const float4*)krow)[l32];
        if (l32 < 16)
            vr = ((const float2*)(vin + rowbase + (size_t)(n*16 + c16)*DIM_ + et*ET_))[l32];
        if (tid < 256) cE = g_E[chunk*256 + tid];
        if (tid < 16) { cg_ = g_gexp[bh*S_ + n*16 + tid]; cqs = g_qs[chunk*16 + tid]; }
        if (tid >= 256) { nab_a = g_a[chunk]; nab_b = g_b[chunk]; }
        if (tid < 128) {
            int c = tid >> 3;
            nqs = g_qs[chunk*16 + c];
            nes = g_esum[chunk*16 + c];
            nxs = g_expns[chunk*16 + c];
        }
    }

    for (int n = 0; n < NS_; n++) {
        // ---- stage ----
        *(float4*)&sq[c16][l32*4] = qr;
        *(float4*)&sk[c16][l32*4] = kr;
        if (l32 < 16) *(float2*)&sv[c16][l32*2] = vr;
        if (tid < 256) sE[tid >> 4][tid & 15] = cE;
        if (tid < 16) { sg[tid] = cg_; sqs[tid] = cqs; }
        float av = nab_a, bv = nab_b;         // current chunk a,b (update thr)
        float rqs = nqs, res = nes, rxs = nxs; // current chunk norm consts
        __syncthreads();

        // ---- prefetch next ----
        if (n + 1 < NS_) {
            int n2 = n + 1, chunk2 = bh*NS_ + n2;
            const float* qrow = qin + rowbase + (size_t)(n2*16 + c16)*DIM_;
            const float* krow = kin + rowbase + (size_t)(n2*16 + c16)*DIM_;
            qr = ((const float4*)qrow)[l32];
            kr = ((const float4*)krow)[l32];
            if (l32 < 16)
                vr = ((const float2*)(vin + rowbase + (size_t)(n2*16 + c16)*DIM_ + et*ET_))[l32];
            if (tid < 256) cE = g_E[chunk2*256 + tid];
            if (tid < 16) { cg_ = g_gexp[bh*S_ + n2*16 + tid]; cqs = g_qs[chunk2*16 + tid]; }
            if (tid >= 256) { nab_a = g_a[chunk2]; nab_b = g_b[chunk2]; }
            if (tid < 128) {
                int c = tid >> 3;
                nqs = g_qs[chunk2*16 + c];
                nes = g_esum[chunk2*16 + c];
                nxs = g_expns[chunk2*16 + c];
            }
        }

        float ks = 0.f;   // ksum for utid<128
        if (tid < 256) {
            // ---- inter: K-split q@Cp + pn partials + E-part ----
            ull acc[4][2];
            float pnp[4];
#pragma unroll
            for (int i = 0; i < 4; i++) { acc[i][0] = 0ull; acc[i][1] = 0ull; pnp[i] = 0.f; }
            int k0 = wid * 16;
#pragma unroll
            for (int kk = 0; kk < 16; kk++) {
                int krr = k0 + kk;
                ull cA = *(const ull*)&sC[krr][eg*4];
                ull cB = *(const ull*)&sC[krr][eg*4 + 2];
                float snv = sn[krr];
#pragma unroll
                for (int i = 0; i < 4; i++) {
                    float qv = sq[cgi + 4*i][krr];
                    ull q2 = pk2(qv, qv);
                    acc[i][0] = ffma2(q2, cA, acc[i][0]);
                    acc[i][1] = ffma2(q2, cB, acc[i][1]);
                    pnp[i] = fmaf(qv, snv, pnp[i]);
                }
            }
#pragma unroll
            for (int i = 0; i < 4; i++) {
                float qsv = sqs[cgi + 4*i];
                ull q2 = pk2(qsv, qsv);
                acc[i][0] = fmul2(acc[i][0], q2);
                acc[i][1] = fmul2(acc[i][1], q2);
            }
#pragma unroll
            for (int rr = 0; rr < 2; rr++) {
                int r = wid*2 + rr;
                ull vA = *(const ull*)&sv[r][eg*4];
                ull vB = *(const ull*)&sv[r][eg*4 + 2];
#pragma unroll
                for (int i = 0; i < 4; i++) {
                    float ev = sE[cgi + 4*i][r];
                    ull e2 = pk2(ev, ev);
                    acc[i][0] = ffma2(e2, vA, acc[i][0]);
                    acc[i][1] = ffma2(e2, vB, acc[i][1]);
                }
            }
#pragma unroll
            for (int i = 0; i < 4; i++) {
                *(ull*)&spart[wid][cgi + 4*i][eg*4]     = acc[i][0];
                *(ull*)&spart[wid][cgi + 4*i][eg*4 + 2] = acc[i][1];
            }
            if (eg == 0) {
#pragma unroll
                for (int i = 0; i < 4; i++) spn[wid][cgi + 4*i] = pnp[i];
            }
        } else {
            // ---- update: acc = k^T (v*gexp); Cf = a*Cf + b*acc ----
            float accf[8][2];
#pragma unroll
            for (int g = 0; g < 8; g++) { accf[g][0] = 0.f; accf[g][1] = 0.f; }
#pragma unroll
            for (int c = 0; c < 16; c++) {
                float2 v2 = *(const float2*)&sv[c][ux*2];
                float gv = sg[c];
                float vgx = v2.x * gv, vgy = v2.y * gv;
                float4 ka = *(const float4*)&sk[c][uyy*8];
                float4 kb = *(const float4*)&sk[c][uyy*8 + 4];
                accf[0][0] = fmaf(ka.x, vgx, accf[0][0]); accf[0][1] = fmaf(ka.x, vgy, accf[0][1]);
                accf[1][0] = fmaf(ka.y, vgx, accf[1][0]); accf[1][1] = fmaf(ka.y, vgy, accf[1][1]);
                accf[2][0] = fmaf(ka.z, vgx, accf[2][0]); accf[2][1] = fmaf(ka.z, vgy, accf[2][1]);
                accf[3][0] = fmaf(ka.w, vgx, accf[3][0]); accf[3][1] = fmaf(ka.w, vgy, accf[3][1]);
                accf[4][0] = fmaf(kb.x, vgx, accf[4][0]); accf[4][1] = fmaf(kb.x, vgy, accf[4][1]);
                accf[5][0] = fmaf(kb.y, vgx, accf[5][0]); accf[5][1] = fmaf(kb.y, vgy, accf[5][1]);
                accf[6][0] = fmaf(kb.z, vgx, accf[6][0]); accf[6][1] = fmaf(kb.z, vgy, accf[6][1]);
                accf[7][0] = fmaf(kb.w, vgx, accf[7][0]); accf[7][1] = fmaf(kb.w, vgy, accf[7][1]);
            }
#pragma unroll
            for (int g = 0; g < 8; g++) {
                Cf[g][0] = fmaf(Cf[g][0], av, accf[g][0] * bv);
                Cf[g][1] = fmaf(Cf[g][1], av, accf[g][1] * bv);
            }
            if (utid < 128) {
#pragma unroll
                for (int c = 0; c < 16; c++)
                    ks = fmaf(sk[c][utid], sg[c], ks);
            }
        }
        __syncthreads();

        if (tid < 128) {
            // ---- reduce partials + norm + store h ----
            int c = tid >> 3, eq = tid & 7;
            float4 hs = make_float4(0.f, 0.f, 0.f, 0.f);
#pragma unroll
            for (int w = 0; w < 8; w++) {
                float4 p = *(const float4*)&spart[w][c][eq*4];
                hs.x += p.x; hs.y += p.y; hs.z += p.z; hs.w += p.w;
            }
            float pn = 0.f;
#pragma unroll
            for (int w = 0; w < 8; w++) pn += spn[w][c];
            float norm = fmaxf(fabsf(res + rqs*pn), rxs) + EPS_;
            float inv = 1.f / norm;
            hs.x *= inv; hs.y *= inv; hs.z *= inv; hs.w *= inv;
            *(float4*)(out + rowbase + (size_t)(n*16 + c)*DIM_ + et*ET_ + eq*4) = hs;
        } else if (tid >= 256) {
            // ---- republish C, update n ----
#pragma unroll
            for (int g = 0; g < 8; g++)
                *(float2*)&sC[uyy*8 + g][ux*2] = make_float2(Cf[g][0], Cf[g][1]);
            if (utid < 128)
                sn[utid] = fmaf(sn[utid], av, ks * bv);
        }
        // loop-top __syncthreads orders phase-2 writes vs next phase-1 reads
    }

    // ---- final states ----
    if (tid >= 256) {
        size_t clb = (size_t)bh * (DH_*DH_);
#pragma unroll
        for (int g = 0; g < 8; g++) {
            size_t o = clb + (size_t)(uyy*8 + g)*DH_ + et*ET_ + ux*2;
            *(float2*)&Cl[o] = make_float2(Cf[g][0], Cf[g][1]);
        }
        if (et == 0 && utid < 128) nl[bh*DH_ + utid] = sn[utid];
    }
}

// ============================================================
// K5: in-place layernorm over out, per (b,s,head) row of 128.
// ============================================================
__global__ __launch_bounds__(256) void k_ln(
    const float* __restrict__ lnw, const float* __restrict__ lnb,
    float* __restrict__ out)
{
    int r = blockIdx.x*8 + (threadIdx.x >> 5);   // row over B*S*NH
    int lane = threadIdx.x & 31;
    int bs = r >> 3, h = r & 7;
    float4* p = (float4*)(out + (size_t)bs*DIM_ + h*DH_);
    float4 x = p[lane];
    float s1 = x.x + x.y + x.z + x.w;
#pragma unroll
    for (int off = 16; off; off >>= 1)
        s1 += __shfl_xor_sync(0xffffffffu, s1, off);
    float mu = s1 * (1.f/128.f);
    float dx = x.x - mu, dy = x.y - mu, dz = x.z - mu, dw = x.w - mu;
    float s2 = dx*dx + dy*dy + dz*dz + dw*dw;
#pragma unroll
    for (int off = 16; off; off >>= 1)
        s2 += __shfl_xor_sync(0xffffffffu, s2, off);
    float rstd = rsqrtf(s2 * (1.f/128.f) + LN_EPS_);
    float4 w = ((const float4*)(lnw + h*DH_))[lane];
    float4 bb = ((const float4*)(lnb + h*DH_))[lane];
    x.x = dx*rstd*(1.f + w.x) + bb.x;
    x.y = dy*rstd*(1.f + w.y) + bb.y;
    x.z = dz*rstd*(1.f + w.z) + bb.z;
    x.w = dw*rstd*(1.f + w.w) + bb.w;
    p[lane] = x;
}

// ============================================================
extern "C" void kernel_launch(void* const* d_in, const int* in_sizes, int n_in,
                              void* d_out, int out_size)
{
    const float* q   = (const float*)d_in[0];
    const float* k   = (const float*)d_in[1];
    const float* v   = (const float*)d_in[2];
    const float* Wi  = (const float*)d_in[3];
    const float* bi  = (const float*)d_in[4];
    const float* Wf  = (const float*)d_in[5];
    const float* bf  = (const float*)d_in[6];
    const float* lnw = (const float*)d_in[7];
    const float* lnb = (const float*)d_in[8];

    float* out = (float*)d_out;
    float* Cl  = out + (size_t)B_*S_*DIM_;       // 8388608
    float* nl  = Cl  + (size_t)BH_*DH_*DH_;      // +524288
    float* ml  = nl  + (size_t)BH_*DH_;          // +4096

    k_gates  <<< (B_*S_)/K1_T, 256 >>>(q, k, v, Wi, bi, Wf, bf);
    k_prep   <<< BH_, 128 >>>(ml);
    k_phaseA <<< NCHUNK, 128 >>>(q, k);
    dim3 gf(4, BH_);
    k_fused3 <<< gf, 512 >>>(q, k, v, out, Cl, nl);
    k_ln     <<< (B_*S_*NH_)/8, 256 >>>(lnw, lnb, out);
}

// round 5
// speedup vs baseline: 2.3442x; 1.0015x over previous
#include <cuda_runtime.h>
#include <math.h>

// ---------------- problem constants ----------------
#define B_    4
#define S_    2048
#define DIM_  1024
#define NH_   8
#define DH_   128
#define CS_   16
#define NS_   128
#define BH_   (B_*NH_)        // 32
#define NCHUNK (BH_*NS_)      // 4096
#define ET_   32              // e-tile width in fused kernel
#define EPS_    1e-6f
#define LN_EPS_ 1e-5f
#define NEG_   -1e30f

typedef unsigned long long ull;

// ---------------- f32x2 packed helpers (sm_103a) ----------------
__device__ __forceinline__ ull pk2(float lo, float hi) {
    ull r; asm("mov.b64 %0, {%1, %2};" : "=l"(r) : "f"(lo), "f"(hi)); return r;
}
__device__ __forceinline__ ull ffma2(ull a, ull b, ull c) {
    ull d; asm("fma.rn.f32x2 %0, %1, %2, %3;" : "=l"(d) : "l"(a), "l"(b), "l"(c)); return d;
}
__device__ __forceinline__ ull fmul2(ull a, ull b) {
    ull d; asm("mul.rn.f32x2 %0, %1, %2;" : "=l"(d) : "l"(a), "l"(b)); return d;
}

// ---------------- scratch (device globals; no allocation) ----------------
__device__ float g_ig   [BH_*S_];
__device__ float g_fg   [BH_*S_];
__device__ float g_lfacc[BH_*S_];
__device__ float g_gexp [BH_*S_];
__device__ float g_mp   [NCHUNK];
__device__ float g_a    [NCHUNK];
__device__ float g_b    [NCHUNK];
__device__ float g_E    [NCHUNK*CS_*CS_]; // unnormalized E per chunk (16x16)
__device__ float g_qs   [NCHUNK*CS_];     // decay*scale per (chunk,c)
__device__ float g_esum [NCHUNK*CS_];     // row sums of E
__device__ float g_expns[NCHUNK*CS_];     // exp(-stab) per (chunk,c)

// ============================================================
// K1: gates.  ig/fg[b,h,s] = <[q|k|v](b,s,:), W[h,:]> + bias
// ============================================================
#define K1_T 8
__global__ __launch_bounds__(256) void k_gates(
    const float* __restrict__ q, const float* __restrict__ k,
    const float* __restrict__ v, const float* __restrict__ Wi,
    const float* __restrict__ bi, const float* __restrict__ Wf,
    const float* __restrict__ bf)
{
    __shared__ float sg[K1_T][1024];
    int tid  = threadIdx.x;
    int base = blockIdx.x * K1_T;            // flattened (b*S + s)
    int w    = tid >> 5;                     // head
    int lane = tid & 31;
    const float* wi = Wi + w*3072;
    const float* wf = Wf + w*3072;

    float acc_i[K1_T], acc_f[K1_T];
#pragma unroll
    for (int t = 0; t < K1_T; t++) { acc_i[t] = 0.f; acc_f[t] = 0.f; }

    for (int seg = 0; seg < 3; seg++) {
        const float* src = (seg == 0) ? q : (seg == 1) ? k : v;
        for (int r = tid; r < K1_T*256; r += 256) {
            int t = r >> 8, d4 = r & 255;
            ((float4*)sg[t])[d4] =
                ((const float4*)(src + (size_t)(base + t)*1024))[d4];
        }
        __syncthreads();
        const float* wis = wi + seg*1024;
        const float* wfs = wf + seg*1024;
#pragma unroll 2
        for (int kk = lane*4; kk < 1024; kk += 128) {
            float4 w4i = *(const float4*)&wis[kk];
            float4 w4f = *(const float4*)&wfs[kk];
#pragma unroll
            for (int t = 0; t < K1_T; t++) {
                float4 g4 = *(const float4*)&sg[t][kk];
                acc_i[t] = fmaf(g4.x, w4i.x, acc_i[t]);
                acc_i[t] = fmaf(g4.y, w4i.y, acc_i[t]);
                acc_i[t] = fmaf(g4.z, w4i.z, acc_i[t]);
                acc_i[t] = fmaf(g4.w, w4i.w, acc_i[t]);
                acc_f[t] = fmaf(g4.x, w4f.x, acc_f[t]);
                acc_f[t] = fmaf(g4.y, w4f.y, acc_f[t]);
                acc_f[t] = fmaf(g4.z, w4f.z, acc_f[t]);
                acc_f[t] = fmaf(g4.w, w4f.w, acc_f[t]);
            }
        }
        __syncthreads();
    }
#pragma unroll
    for (int t = 0; t < K1_T; t++) {
#pragma unroll
        for (int off = 16; off; off >>= 1) {
            acc_i[t] += __shfl_xor_sync(0xffffffffu, acc_i[t], off);
            acc_f[t] += __shfl_xor_sync(0xffffffffu, acc_f[t], off);
        }
    }
    if (lane == 0) {
        float biv = bi[w], bfv = bf[w];
#pragma unroll
        for (int t = 0; t < K1_T; t++) {
            int bs = base + t;
            int b = bs >> 11, s = bs & 2047;
            int idx = (b*NH_ + w)*S_ + s;
            g_ig[idx] = acc_i[t] + biv;
            g_fg[idx] = acc_f[t] + bfv;
        }
    }
}

// ============================================================
// K2: per-bh prep: logsigmoid cumsum, gexp, and the (a,b,mp)
// max-plus scan over 128 chunks. One block (128 thr) per bh;
// thread n owns chunk n.
// ============================================================
__global__ __launch_bounds__(128) void k_prep(float* __restrict__ ml_out)
{
    __shared__ float wLs[4], wMs[4];
    int bh = blockIdx.x;
    int n  = threadIdx.x;           // chunk
    int lane = n & 31, wid = n >> 5;
    int base = bh*S_ + n*16;

    float fg[16], ig[16];
#pragma unroll
    for (int i = 0; i < 4; i++) {
        float4 f4 = *(const float4*)&g_fg[base + i*4];
        float4 i4 = *(const float4*)&g_ig[base + i*4];
        fg[i*4+0]=f4.x; fg[i*4+1]=f4.y; fg[i*4+2]=f4.z; fg[i*4+3]=f4.w;
        ig[i*4+0]=i4.x; ig[i*4+1]=i4.y; ig[i*4+2]=i4.z; ig[i*4+3]=i4.w;
    }
    float lfacc[16];
    float acc = 0.f;
#pragma unroll
    for (int c = 0; c < 16; c++) {
        float f = fg[c];
        float lf = fminf(f, 0.f) - log1pf(expf(-fabsf(f)));
        acc += lf;
        lfacc[c] = acc;
    }
    float lfl = lfacc[15];
    float lg[16];
    float mloc = NEG_;
#pragma unroll
    for (int c = 0; c < 16; c++) {
        lg[c] = ig[c] - lfacc[c] + lfl;
        mloc = fmaxf(mloc, lg[c]);
    }
#pragma unroll
    for (int i = 0; i < 4; i++) {
        float4 a4, g4;
        a4.x=lfacc[i*4+0]; a4.y=lfacc[i*4+1]; a4.z=lfacc[i*4+2]; a4.w=lfacc[i*4+3];
        g4.x=expf(lg[i*4+0]-mloc); g4.y=expf(lg[i*4+1]-mloc);
        g4.z=expf(lg[i*4+2]-mloc); g4.w=expf(lg[i*4+3]-mloc);
        *(float4*)&g_lfacc[base + i*4] = a4;
        *(float4*)&g_gexp [base + i*4] = g4;
    }

    // max-plus scan over chunks: f(m) = max(m + L, M)
    float L = lfl, M = mloc;
#pragma unroll
    for (int off = 1; off < 32; off <<= 1) {
        float Lp = __shfl_up_sync(0xffffffffu, L, off);
        float Mp = __shfl_up_sync(0xffffffffu, M, off);
        if (lane >= off) { M = fmaxf(Mp + L, M); L = Lp + L; }
    }
    if (lane == 31) { wLs[wid] = L; wMs[wid] = M; }
    __syncthreads();
    float PL = 0.f, PM = NEG_;
#pragma unroll
    for (int ww = 0; ww < 4; ww++) {
        if (ww < wid) { PM = fmaxf(PM + wLs[ww], wMs[ww]); PL += wLs[ww]; }
    }
    // exclusive within warp
    float Lex_w = __shfl_up_sync(0xffffffffu, L, 1);
    float Mex_w = __shfl_up_sync(0xffffffffu, M, 1);
    if (lane == 0) { Lex_w = 0.f; Mex_w = NEG_; }
    float Lex = PL + Lex_w;
    float Mex = fmaxf(PM + Lex_w, Mex_w);
    float mp = fmaxf(Lex, Mex);               // m before chunk n (m0 = 0)
    float Linc = PL + L;
    float Minc = fmaxf(PM + L, M);
    float m = fmaxf(Linc, Minc);              // m after chunk n

    int idx = bh*NS_ + n;
    g_a [idx] = expf(lfl + mp - m);
    g_b [idx] = expf(mloc - m);
    g_mp[idx] = mp;
    if (n == NS_-1) ml_out[bh] = m;
}

// ============================================================
// K3: Phase A per chunk: unnormalized E (16x16), Esum, decay,
// exp(-stab). One block (128 thr) per chunk.
// ============================================================
#define PAD 129
__global__ __launch_bounds__(128) void k_phaseA(
    const float* __restrict__ qin, const float* __restrict__ kin)
{
    __shared__ float sq [CS_][PAD];
    __shared__ float sk [CS_][PAD];
    __shared__ float slf[CS_], sig[CS_];
    __shared__ float smp;

    int chunk = blockIdx.x;
    int bh = chunk >> 7, n = chunk & 127;
    int b = bh >> 3, h = bh & 7;
    int tid = threadIdx.x;
    const float scale = 0.08838834764831845f; // 1/sqrt(128)

    for (int r = tid; r < CS_*DH_; r += 128) {
        int c = r >> 7, d = r & 127;
        size_t gidx = (size_t)(b*S_ + n*16 + c)*DIM_ + h*DH_ + d;
        sq[c][d] = qin[gidx] * scale;
        sk[c][d] = kin[gidx];
    }
    if (tid < 16) {
        slf[tid] = g_lfacc[bh*S_ + n*16 + tid];
        sig[tid] = g_ig  [bh*S_ + n*16 + tid];
    }
    if (tid == 0) smp = g_mp[chunk];
    __syncthreads();

    int c  = tid >> 3;
    int jj = tid & 7;
    int j0 = 2*jj, j1 = 2*jj + 1;
    float qk0 = 0.f, qk1 = 0.f;
#pragma unroll 4
    for (int d = 0; d < DH_; d++) {
        float qv = sq[c][d];
        qk0 = fmaf(qv, sk[j0][d], qk0);
        qk1 = fmaf(qv, sk[j1][d], qk1);
    }
    float mp  = smp;
    float lD0 = ((j0 > c) ? NEG_ : (slf[c] - slf[j0])) + sig[j0];
    float lD1 = ((j1 > c) ? NEG_ : (slf[c] - slf[j1])) + sig[j1];
    float mrow = fmaxf(lD0, lD1);
#pragma unroll
    for (int off = 4; off; off >>= 1)
        mrow = fmaxf(mrow, __shfl_xor_sync(0xffffffffu, mrow, off, 8));
    float stab  = fmaxf(mrow, mp + slf[c]);
    float decay = expf(mp + slf[c] - stab);
    float E0 = qk0 * expf(lD0 - stab);
    float E1 = qk1 * expf(lD1 - stab);
    float Esum = E0 + E1;
#pragma unroll
    for (int off = 4; off; off >>= 1)
        Esum += __shfl_xor_sync(0xffffffffu, Esum, off, 8);
    g_E[chunk*256 + c*16 + j0] = E0;
    g_E[chunk*256 + c*16 + j1] = E1;
    if (jj == 0) {
        g_qs   [chunk*16 + c] = decay * scale;
        g_esum [chunk*16 + c] = Esum;
        g_expns[chunk*16 + c] = expf(-stab);
    }
}

// ============================================================
// K4: fused scan + output (v3): 512 threads, warp-specialized.
//  warps 0-7 : inter  hraw = qs*(q@Cp) + E_un@v  (K-split), pn partials
//  warps 8-15: C state in regs; kv update; n-state scan; republish sC
//  epilogue  : reduce partials, invnorm row scale, store h
// ============================================================
__global__ __launch_bounds__(512, 1) void k_fused3(
    const float* __restrict__ qin, const float* __restrict__ kin,
    const float* __restrict__ vin, float* __restrict__ out,
    float* __restrict__ Cl, float* __restrict__ nl)
{
    __shared__ float sq[CS_][132];
    __shared__ float sk[CS_][132];
    __shared__ float sv[CS_][36];
    __shared__ float sE[CS_][17];
    __shared__ float spart[8][CS_][36];
    __shared__ float spn[8][CS_];
    __shared__ float sC[DH_][ET_];
    __shared__ float sn[DH_];
    __shared__ float sg[CS_], sqs[CS_];

    int et = blockIdx.x;      // 0..3
    int bh = blockIdx.y;      // 0..31
    int b = bh >> 3, h = bh & 7;
    int tid = threadIdx.x;
    int wid = tid >> 5;
    int lane = tid & 31;

    size_t rowbase = (size_t)(b*S_)*DIM_ + h*DH_;

    // zero state
    for (int i = tid; i < DH_*ET_; i += 512) (&sC[0][0])[i] = 0.f;
    if (tid < DH_) sn[tid] = 0.f;

    // staging map
    int c16 = tid >> 5, l32 = tid & 31;

    // inter role
    int cgi = lane >> 3, eg = lane & 7;
    // update role
    int utid = tid - 256;
    int ux = utid & 15, uyy = (utid >= 0) ? (utid >> 4) : 0;

    float Cf[8][2];
#pragma unroll
    for (int g = 0; g < 8; g++) { Cf[g][0] = 0.f; Cf[g][1] = 0.f; }

    // prefetch regs
    float4 qr, kr;
    float2 vr = make_float2(0.f, 0.f);
    float cE = 0.f, cg_ = 0.f, cqs = 0.f;
    float nab_a = 0.f, nab_b = 0.f;          // update threads
    float nqs = 0.f, nes = 0.f, nxs = 0.f;   // reduce threads (tid<128)

    {   // prefetch chunk 0
        int n = 0, chunk = bh*NS_;
        const float* qrow = qin + rowbase + (size_t)(n*16 + c16)*DIM_;
        const float* krow = kin + rowbase + (size_t)(n*16 + c16)*DIM_;
        qr = ((const float4*)qrow)[l32];
        kr = ((const float4*)krow)[l32];
        if (l32 < 16)
            vr = ((const float2*)(vin + rowbase + (size_t)(n*16 + c16)*DIM_ + et*ET_))[l32];
        if (tid < 256) cE = g_E[chunk*256 + tid];
        if (tid < 16) { cg_ = g_gexp[bh*S_ + n*16 + tid]; cqs = g_qs[chunk*16 + tid]; }
        if (tid >= 256) { nab_a = g_a[chunk]; nab_b = g_b[chunk]; }
        if (tid < 128) {
            int c = tid >> 3;
            nqs = g_qs[chunk*16 + c];
            nes = g_esum[chunk*16 + c];
            nxs = g_expns[chunk*16 + c];
        }
    }

    for (int n = 0; n < NS_; n++) {
        // ---- stage ----
        *(float4*)&sq[c16][l32*4] = qr;
        *(float4*)&sk[c16][l32*4] = kr;
        if (l32 < 16) *(float2*)&sv[c16][l32*2] = vr;
        if (tid < 256) sE[tid >> 4][tid & 15] = cE;
        if (tid < 16) { sg[tid] = cg_; sqs[tid] = cqs; }
        float av = nab_a, bv = nab_b;         // current chunk a,b (update thr)
        float rqs = nqs, res = nes, rxs = nxs; // current chunk norm consts
        __syncthreads();

        // ---- prefetch next ----
        if (n + 1 < NS_) {
            int n2 = n + 1, chunk2 = bh*NS_ + n2;
            const float* qrow = qin + rowbase + (size_t)(n2*16 + c16)*DIM_;
            const float* krow = kin + rowbase + (size_t)(n2*16 + c16)*DIM_;
            qr = ((const float4*)qrow)[l32];
            kr = ((const float4*)krow)[l32];
            if (l32 < 16)
                vr = ((const float2*)(vin + rowbase + (size_t)(n2*16 + c16)*DIM_ + et*ET_))[l32];
            if (tid < 256) cE = g_E[chunk2*256 + tid];
            if (tid < 16) { cg_ = g_gexp[bh*S_ + n2*16 + tid]; cqs = g_qs[chunk2*16 + tid]; }
            if (tid >= 256) { nab_a = g_a[chunk2]; nab_b = g_b[chunk2]; }
            if (tid < 128) {
                int c = tid >> 3;
                nqs = g_qs[chunk2*16 + c];
                nes = g_esum[chunk2*16 + c];
                nxs = g_expns[chunk2*16 + c];
            }
        }

        float ks = 0.f;   // ksum for utid<128
        if (tid < 256) {
            // ---- inter: K-split q@Cp + pn partials + E-part ----
            ull acc[4][2];
            float pnp[4];
#pragma unroll
            for (int i = 0; i < 4; i++) { acc[i][0] = 0ull; acc[i][1] = 0ull; pnp[i] = 0.f; }
            int k0 = wid * 16;
#pragma unroll
            for (int kk = 0; kk < 16; kk++) {
                int krr = k0 + kk;
                ull cA = *(const ull*)&sC[krr][eg*4];
                ull cB = *(const ull*)&sC[krr][eg*4 + 2];
                float snv = sn[krr];
#pragma unroll
                for (int i = 0; i < 4; i++) {
                    float qv = sq[cgi + 4*i][krr];
                    ull q2 = pk2(qv, qv);
                    acc[i][0] = ffma2(q2, cA, acc[i][0]);
                    acc[i][1] = ffma2(q2, cB, acc[i][1]);
                    pnp[i] = fmaf(qv, snv, pnp[i]);
                }
            }
#pragma unroll
            for (int i = 0; i < 4; i++) {
                float qsv = sqs[cgi + 4*i];
                ull q2 = pk2(qsv, qsv);
                acc[i][0] = fmul2(acc[i][0], q2);
                acc[i][1] = fmul2(acc[i][1], q2);
            }
#pragma unroll
            for (int rr = 0; rr < 2; rr++) {
                int r = wid*2 + rr;
                ull vA = *(const ull*)&sv[r][eg*4];
                ull vB = *(const ull*)&sv[r][eg*4 + 2];
#pragma unroll
                for (int i = 0; i < 4; i++) {
                    float ev = sE[cgi + 4*i][r];
                    ull e2 = pk2(ev, ev);
                    acc[i][0] = ffma2(e2, vA, acc[i][0]);
                    acc[i][1] = ffma2(e2, vB, acc[i][1]);
                }
            }
#pragma unroll
            for (int i = 0; i < 4; i++) {
                *(ull*)&spart[wid][cgi + 4*i][eg*4]     = acc[i][0];
                *(ull*)&spart[wid][cgi + 4*i][eg*4 + 2] = acc[i][1];
            }
            if (eg == 0) {
#pragma unroll
                for (int i = 0; i < 4; i++) spn[wid][cgi + 4*i] = pnp[i];
            }
        } else {
            // ---- update: acc = k^T (v*gexp); Cf = a*Cf + b*acc ----
            float accf[8][2];
#pragma unroll
            for (int g = 0; g < 8; g++) { accf[g][0] = 0.f; accf[g][1] = 0.f; }
#pragma unroll
            for (int c = 0; c < 16; c++) {
                float2 v2 = *(const float2*)&sv[c][ux*2];
                float gv = sg[c];
                float vgx = v2.x * gv, vgy = v2.y * gv;
                float4 ka = *(const float4*)&sk[c][uyy*8];
                float4 kb = *(const float4*)&sk[c][uyy*8 + 4];
                accf[0][0] = fmaf(ka.x, vgx, accf[0][0]); accf[0][1] = fmaf(ka.x, vgy, accf[0][1]);
                accf[1][0] = fmaf(ka.y, vgx, accf[1][0]); accf[1][1] = fmaf(ka.y, vgy, accf[1][1]);
                accf[2][0] = fmaf(ka.z, vgx, accf[2][0]); accf[2][1] = fmaf(ka.z, vgy, accf[2][1]);
                accf[3][0] = fmaf(ka.w, vgx, accf[3][0]); accf[3][1] = fmaf(ka.w, vgy, accf[3][1]);
                accf[4][0] = fmaf(kb.x, vgx, accf[4][0]); accf[4][1] = fmaf(kb.x, vgy, accf[4][1]);
                accf[5][0] = fmaf(kb.y, vgx, accf[5][0]); accf[5][1] = fmaf(kb.y, vgy, accf[5][1]);
                accf[6][0] = fmaf(kb.z, vgx, accf[6][0]); accf[6][1] = fmaf(kb.z, vgy, accf[6][1]);
                accf[7][0] = fmaf(kb.w, vgx, accf[7][0]); accf[7][1] = fmaf(kb.w, vgy, accf[7][1]);
            }
#pragma unroll
            for (int g = 0; g < 8; g++) {
                Cf[g][0] = fmaf(Cf[g][0], av, accf[g][0] * bv);
                Cf[g][1] = fmaf(Cf[g][1], av, accf[g][1] * bv);
            }
            if (utid < 128) {
#pragma unroll
                for (int c = 0; c < 16; c++)
                    ks = fmaf(sk[c][utid], sg[c], ks);
            }
        }
        __syncthreads();

        if (tid < 128) {
            // ---- reduce partials + norm + store h ----
            int c = tid >> 3, eq = tid & 7;
            float4 hs = make_float4(0.f, 0.f, 0.f, 0.f);
#pragma unroll
            for (int w = 0; w < 8; w++) {
                float4 p = *(const float4*)&spart[w][c][eq*4];
                hs.x += p.x; hs.y += p.y; hs.z += p.z; hs.w += p.w;
            }
            float pn = 0.f;
#pragma unroll
            for (int w = 0; w < 8; w++) pn += spn[w][c];
            float norm = fmaxf(fabsf(res + rqs*pn), rxs) + EPS_;
            float inv = 1.f / norm;
            hs.x *= inv; hs.y *= inv; hs.z *= inv; hs.w *= inv;
            *(float4*)(out + rowbase + (size_t)(n*16 + c)*DIM_ + et*ET_ + eq*4) = hs;
        } else if (tid >= 256) {
            // ---- republish C, update n ----
#pragma unroll
            for (int g = 0; g < 8; g++)
                *(float2*)&sC[uyy*8 + g][ux*2] = make_float2(Cf[g][0], Cf[g][1]);
            if (utid < 128)
                sn[utid] = fmaf(sn[utid], av, ks * bv);
        }
        // loop-top __syncthreads orders phase-2 writes vs next phase-1 reads
    }

    // ---- final states ----
    if (tid >= 256) {
        size_t clb = (size_t)bh * (DH_*DH_);
#pragma unroll
        for (int g = 0; g < 8; g++) {
            size_t o = clb + (size_t)(uyy*8 + g)*DH_ + et*ET_ + ux*2;
            *(float2*)&Cl[o] = make_float2(Cf[g][0], Cf[g][1]);
        }
        if (et == 0 && utid < 128) nl[bh*DH_ + utid] = sn[utid];
    }
}

// ============================================================
// K5: in-place layernorm over out, per (b,s,head) row of 128.
// ============================================================
__global__ __launch_bounds__(256) void k_ln(
    const float* __restrict__ lnw, const float* __restrict__ lnb,
    float* __restrict__ out)
{
    int r = blockIdx.x*8 + (threadIdx.x >> 5);   // row over B*S*NH
    int lane = threadIdx.x & 31;
    int bs = r >> 3, h = r & 7;
    float4* p = (float4*)(out + (size_t)bs*DIM_ + h*DH_);
    float4 x = p[lane];
    float s1 = x.x + x.y + x.z + x.w;
#pragma unroll
    for (int off = 16; off; off >>= 1)
        s1 += __shfl_xor_sync(0xffffffffu, s1, off);
    float mu = s1 * (1.f/128.f);
    float dx = x.x - mu, dy = x.y - mu, dz = x.z - mu, dw = x.w - mu;
    float s2 = dx*dx + dy*dy + dz*dz + dw*dw;
#pragma unroll
    for (int off = 16; off; off >>= 1)
        s2 += __shfl_xor_sync(0xffffffffu, s2, off);
    float rstd = rsqrtf(s2 * (1.f/128.f) + LN_EPS_);
    float4 w = ((const float4*)(lnw + h*DH_))[lane];
    float4 bb = ((const float4*)(lnb + h*DH_))[lane];
    x.x = dx*rstd*(1.f + w.x) + bb.x;
    x.y = dy*rstd*(1.f + w.y) + bb.y;
    x.z = dz*rstd*(1.f + w.z) + bb.z;
    x.w = dw*rstd*(1.f + w.w) + bb.w;
    p[lane] = x;
}

// ============================================================
extern "C" void kernel_launch(void* const* d_in, const int* in_sizes, int n_in,
                              void* d_out, int out_size)
{
    const float* q   = (const float*)d_in[0];
    const float* k   = (const float*)d_in[1];
    const float* v   = (const float*)d_in[2];
    const float* Wi  = (const float*)d_in[3];
    const float* bi  = (const float*)d_in[4];
    const float* Wf  = (const float*)d_in[5];
    const float* bf  = (const float*)d_in[6];
    const float* lnw = (const float*)d_in[7];
    const float* lnb = (const float*)d_in[8];

    float* out = (float*)d_out;
    float* Cl  = out + (size_t)B_*S_*DIM_;       // 8388608
    float* nl  = Cl  + (size_t)BH_*DH_*DH_;      // +524288
    float* ml  = nl  + (size_t)BH_*DH_;          // +4096

    k_gates  <<< (B_*S_)/K1_T, 256 >>>(q, k, v, Wi, bi, Wf, bf);
    k_prep   <<< BH_, 128 >>>(ml);
    k_phaseA <<< NCHUNK, 128 >>>(q, k);
    dim3 gf(4, BH_);
    k_fused3 <<< gf, 512 >>>(q, k, v, out, Cl, nl);
    k_ln     <<< (B_*S_*NH_)/8, 256 >>>(lnw, lnb, out);
}

// round 6
// speedup vs baseline: 2.4229x; 1.0335x over previous
#include <cuda_runtime.h>
#include <math.h>

// ---------------- problem constants ----------------
#define B_    4
#define S_    2048
#define DIM_  1024
#define NH_   8
#define DH_   128
#define CS_   16
#define NS_   128
#define BH_   (B_*NH_)        // 32
#define NCHUNK (BH_*NS_)      // 4096
#define ET_   32              // e-tile width in fused kernel
#define EPS_    1e-6f
#define LN_EPS_ 1e-5f
#define NEG_   -1e30f

typedef unsigned long long ull;

// ---------------- f32x2 packed helpers (sm_103a) ----------------
__device__ __forceinline__ ull pk2(float lo, float hi) {
    ull r; asm("mov.b64 %0, {%1, %2};" : "=l"(r) : "f"(lo), "f"(hi)); return r;
}
__device__ __forceinline__ ull ffma2(ull a, ull b, ull c) {
    ull d; asm("fma.rn.f32x2 %0, %1, %2, %3;" : "=l"(d) : "l"(a), "l"(b), "l"(c)); return d;
}
__device__ __forceinline__ ull fmul2(ull a, ull b) {
    ull d; asm("mul.rn.f32x2 %0, %1, %2;" : "=l"(d) : "l"(a), "l"(b)); return d;
}

// ---------------- scratch (device globals; no allocation) ----------------
__device__ float g_ig   [BH_*S_];
__device__ float g_fg   [BH_*S_];
__device__ float g_lfacc[BH_*S_];
__device__ float g_gexp [BH_*S_];
__device__ float g_mp   [NCHUNK];
__device__ float g_a    [NCHUNK];
__device__ float g_b    [NCHUNK];
__device__ float g_E    [NCHUNK*CS_*CS_]; // unnormalized E per chunk (16x16)
__device__ float g_qs   [NCHUNK*CS_];     // decay*scale per (chunk,c)
__device__ float g_esum [NCHUNK*CS_];     // row sums of E
__device__ float g_expns[NCHUNK*CS_];     // exp(-stab) per (chunk,c)

// ============================================================
// K1: gates.
// ============================================================
#define K1_T 8
__global__ __launch_bounds__(256) void k_gates(
    const float* __restrict__ q, const float* __restrict__ k,
    const float* __restrict__ v, const float* __restrict__ Wi,
    const float* __restrict__ bi, const float* __restrict__ Wf,
    const float* __restrict__ bf)
{
    __shared__ float sg[K1_T][1024];
    int tid  = threadIdx.x;
    int base = blockIdx.x * K1_T;
    int w    = tid >> 5;
    int lane = tid & 31;
    const float* wi = Wi + w*3072;
    const float* wf = Wf + w*3072;

    float acc_i[K1_T], acc_f[K1_T];
#pragma unroll
    for (int t = 0; t < K1_T; t++) { acc_i[t] = 0.f; acc_f[t] = 0.f; }

    for (int seg = 0; seg < 3; seg++) {
        const float* src = (seg == 0) ? q : (seg == 1) ? k : v;
        for (int r = tid; r < K1_T*256; r += 256) {
            int t = r >> 8, d4 = r & 255;
            ((float4*)sg[t])[d4] =
                ((const float4*)(src + (size_t)(base + t)*1024))[d4];
        }
        __syncthreads();
        const float* wis = wi + seg*1024;
        const float* wfs = wf + seg*1024;
#pragma unroll 2
        for (int kk = lane*4; kk < 1024; kk += 128) {
            float4 w4i = *(const float4*)&wis[kk];
            float4 w4f = *(const float4*)&wfs[kk];
#pragma unroll
            for (int t = 0; t < K1_T; t++) {
                float4 g4 = *(const float4*)&sg[t][kk];
                acc_i[t] = fmaf(g4.x, w4i.x, acc_i[t]);
                acc_i[t] = fmaf(g4.y, w4i.y, acc_i[t]);
                acc_i[t] = fmaf(g4.z, w4i.z, acc_i[t]);
                acc_i[t] = fmaf(g4.w, w4i.w, acc_i[t]);
                acc_f[t] = fmaf(g4.x, w4f.x, acc_f[t]);
                acc_f[t] = fmaf(g4.y, w4f.y, acc_f[t]);
                acc_f[t] = fmaf(g4.z, w4f.z, acc_f[t]);
                acc_f[t] = fmaf(g4.w, w4f.w, acc_f[t]);
            }
        }
        __syncthreads();
    }
#pragma unroll
    for (int t = 0; t < K1_T; t++) {
#pragma unroll
        for (int off = 16; off; off >>= 1) {
            acc_i[t] += __shfl_xor_sync(0xffffffffu, acc_i[t], off);
            acc_f[t] += __shfl_xor_sync(0xffffffffu, acc_f[t], off);
        }
    }
    if (lane == 0) {
        float biv = bi[w], bfv = bf[w];
#pragma unroll
        for (int t = 0; t < K1_T; t++) {
            int bs = base + t;
            int b = bs >> 11, s = bs & 2047;
            int idx = (b*NH_ + w)*S_ + s;
            g_ig[idx] = acc_i[t] + biv;
            g_fg[idx] = acc_f[t] + bfv;
        }
    }
}

// ============================================================
// K2: per-bh prep: logsigmoid cumsum, gexp, (a,b,mp) max-plus scan.
// ============================================================
__global__ __launch_bounds__(128) void k_prep(float* __restrict__ ml_out)
{
    __shared__ float wLs[4], wMs[4];
    int bh = blockIdx.x;
    int n  = threadIdx.x;
    int lane = n & 31, wid = n >> 5;
    int base = bh*S_ + n*16;

    float fg[16], ig[16];
#pragma unroll
    for (int i = 0; i < 4; i++) {
        float4 f4 = *(const float4*)&g_fg[base + i*4];
        float4 i4 = *(const float4*)&g_ig[base + i*4];
        fg[i*4+0]=f4.x; fg[i*4+1]=f4.y; fg[i*4+2]=f4.z; fg[i*4+3]=f4.w;
        ig[i*4+0]=i4.x; ig[i*4+1]=i4.y; ig[i*4+2]=i4.z; ig[i*4+3]=i4.w;
    }
    float lfacc[16];
    float acc = 0.f;
#pragma unroll
    for (int c = 0; c < 16; c++) {
        float f = fg[c];
        float lf = fminf(f, 0.f) - log1pf(expf(-fabsf(f)));
        acc += lf;
        lfacc[c] = acc;
    }
    float lfl = lfacc[15];
    float lg[16];
    float mloc = NEG_;
#pragma unroll
    for (int c = 0; c < 16; c++) {
        lg[c] = ig[c] - lfacc[c] + lfl;
        mloc = fmaxf(mloc, lg[c]);
    }
#pragma unroll
    for (int i = 0; i < 4; i++) {
        float4 a4, g4;
        a4.x=lfacc[i*4+0]; a4.y=lfacc[i*4+1]; a4.z=lfacc[i*4+2]; a4.w=lfacc[i*4+3];
        g4.x=expf(lg[i*4+0]-mloc); g4.y=expf(lg[i*4+1]-mloc);
        g4.z=expf(lg[i*4+2]-mloc); g4.w=expf(lg[i*4+3]-mloc);
        *(float4*)&g_lfacc[base + i*4] = a4;
        *(float4*)&g_gexp [base + i*4] = g4;
    }

    float L = lfl, M = mloc;
#pragma unroll
    for (int off = 1; off < 32; off <<= 1) {
        float Lp = __shfl_up_sync(0xffffffffu, L, off);
        float Mp = __shfl_up_sync(0xffffffffu, M, off);
        if (lane >= off) { M = fmaxf(Mp + L, M); L = Lp + L; }
    }
    if (lane == 31) { wLs[wid] = L; wMs[wid] = M; }
    __syncthreads();
    float PL = 0.f, PM = NEG_;
#pragma unroll
    for (int ww = 0; ww < 4; ww++) {
        if (ww < wid) { PM = fmaxf(PM + wLs[ww], wMs[ww]); PL += wLs[ww]; }
    }
    float Lex_w = __shfl_up_sync(0xffffffffu, L, 1);
    float Mex_w = __shfl_up_sync(0xffffffffu, M, 1);
    if (lane == 0) { Lex_w = 0.f; Mex_w = NEG_; }
    float Lex = PL + Lex_w;
    float Mex = fmaxf(PM + Lex_w, Mex_w);
    float mp = fmaxf(Lex, Mex);
    float Linc = PL + L;
    float Minc = fmaxf(PM + L, M);
    float m = fmaxf(Linc, Minc);

    int idx = bh*NS_ + n;
    g_a [idx] = expf(lfl + mp - m);
    g_b [idx] = expf(mloc - m);
    g_mp[idx] = mp;
    if (n == NS_-1) ml_out[bh] = m;
}

// ============================================================
// K3: Phase A per chunk: unnormalized E, Esum, decay, exp(-stab).
// ============================================================
#define PAD 129
__global__ __launch_bounds__(128) void k_phaseA(
    const float* __restrict__ qin, const float* __restrict__ kin)
{
    __shared__ float sq [CS_][PAD];
    __shared__ float sk [CS_][PAD];
    __shared__ float slf[CS_], sig[CS_];
    __shared__ float smp;

    int chunk = blockIdx.x;
    int bh = chunk >> 7, n = chunk & 127;
    int b = bh >> 3, h = bh & 7;
    int tid = threadIdx.x;
    const float scale = 0.08838834764831845f; // 1/sqrt(128)

    for (int r = tid; r < CS_*DH_; r += 128) {
        int c = r >> 7, d = r & 127;
        size_t gidx = (size_t)(b*S_ + n*16 + c)*DIM_ + h*DH_ + d;
        sq[c][d] = qin[gidx] * scale;
        sk[c][d] = kin[gidx];
    }
    if (tid < 16) {
        slf[tid] = g_lfacc[bh*S_ + n*16 + tid];
        sig[tid] = g_ig  [bh*S_ + n*16 + tid];
    }
    if (tid == 0) smp = g_mp[chunk];
    __syncthreads();

    int c  = tid >> 3;
    int jj = tid & 7;
    int j0 = 2*jj, j1 = 2*jj + 1;
    float qk0 = 0.f, qk1 = 0.f;
#pragma unroll 4
    for (int d = 0; d < DH_; d++) {
        float qv = sq[c][d];
        qk0 = fmaf(qv, sk[j0][d], qk0);
        qk1 = fmaf(qv, sk[j1][d], qk1);
    }
    float mp  = smp;
    float lD0 = ((j0 > c) ? NEG_ : (slf[c] - slf[j0])) + sig[j0];
    float lD1 = ((j1 > c) ? NEG_ : (slf[c] - slf[j1])) + sig[j1];
    float mrow = fmaxf(lD0, lD1);
#pragma unroll
    for (int off = 4; off; off >>= 1)
        mrow = fmaxf(mrow, __shfl_xor_sync(0xffffffffu, mrow, off, 8));
    float stab  = fmaxf(mrow, mp + slf[c]);
    float decay = expf(mp + slf[c] - stab);
    float E0 = qk0 * expf(lD0 - stab);
    float E1 = qk1 * expf(lD1 - stab);
    float Esum = E0 + E1;
#pragma unroll
    for (int off = 4; off; off >>= 1)
        Esum += __shfl_xor_sync(0xffffffffu, Esum, off, 8);
    g_E[chunk*256 + c*16 + j0] = E0;
    g_E[chunk*256 + c*16 + j1] = E1;
    if (jj == 0) {
        g_qs   [chunk*16 + c] = decay * scale;
        g_esum [chunk*16 + c] = Esum;
        g_expns[chunk*16 + c] = expf(-stab);
    }
}

// ============================================================
// K4: fused scan + output (v5): vectorized smem access.
//  warps 0-7 : inter  hraw = qs*(q@Cp) + E_un@v  (K-split), pn partials
//  warps 8-15: C state in regs; kv update; n-state scan; republish sC
// ============================================================
__global__ __launch_bounds__(512, 1) void k_fused5(
    const float* __restrict__ qin, const float* __restrict__ kin,
    const float* __restrict__ vin, float* __restrict__ out,
    float* __restrict__ Cl, float* __restrict__ nl)
{
    __shared__ float sq[CS_][132];
    __shared__ float sk[CS_][132];
    __shared__ float sv[CS_][36];
    __shared__ float sE[CS_][17];
    __shared__ float spart[8][CS_][36];
    __shared__ float spn[8][CS_];
    __shared__ float sC[DH_][ET_];
    __shared__ float sn[DH_];
    __shared__ float sgx[CS_], sqs[CS_];

    int et = blockIdx.x;      // 0..3
    int bh = blockIdx.y;      // 0..31
    int b = bh >> 3, h = bh & 7;
    int tid = threadIdx.x;
    int wid = tid >> 5;
    int lane = tid & 31;

    size_t rowbase = (size_t)(b*S_)*DIM_ + h*DH_;

    for (int i = tid; i < DH_*ET_; i += 512) (&sC[0][0])[i] = 0.f;
    if (tid < DH_) sn[tid] = 0.f;

    int c16 = tid >> 5, l32 = tid & 31;

    // inter role
    int cgi = lane >> 3, eg = lane & 7;
    // update role
    int utid = tid - 256;
    int ux = utid & 15, uyy = (utid >= 0) ? (utid >> 4) : 0;

    float Cf[8][2];
#pragma unroll
    for (int g = 0; g < 8; g++) { Cf[g][0] = 0.f; Cf[g][1] = 0.f; }

    // prefetch regs
    float4 qr, kr;
    float2 vr = make_float2(0.f, 0.f);
    float cE = 0.f, cg_ = 0.f, cqs = 0.f;
    float nab_a = 0.f, nab_b = 0.f;
    float nqs = 0.f, nes = 0.f, nxs = 0.f;

    {   // prefetch chunk 0
        int n = 0, chunk = bh*NS_;
        const float* qrow = qin + rowbase + (size_t)(n*16 + c16)*DIM_;
        const float* krow = kin + rowbase + (size_t)(n*16 + c16)*DIM_;
        qr = ((const float4*)qrow)[l32];
        kr = ((const float4*)krow)[l32];
        if (l32 < 16)
            vr = ((const float2*)(vin + rowbase + (size_t)(n*16 + c16)*DIM_ + et*ET_))[l32];
        if (tid < 256) cE = g_E[chunk*256 + tid];
        if (tid < 16) { cg_ = g_gexp[bh*S_ + n*16 + tid]; cqs = g_qs[chunk*16 + tid]; }
        if (tid >= 256) { nab_a = g_a[chunk]; nab_b = g_b[chunk]; }
        if (tid < 128) {
            int c = tid >> 3;
            nqs = g_qs[chunk*16 + c];
            nes = g_esum[chunk*16 + c];
            nxs = g_expns[chunk*16 + c];
        }
    }

    for (int n = 0; n < NS_; n++) {
        // ---- stage ----
        *(float4*)&sq[c16][l32*4] = qr;
        *(float4*)&sk[c16][l32*4] = kr;
        if (l32 < 16) *(float2*)&sv[c16][l32*2] = vr;
        if (tid < 256) sE[tid >> 4][tid & 15] = cE;
        if (tid < 16) { sgx[tid] = cg_; sqs[tid] = cqs; }
        float av = nab_a, bv = nab_b;
        float rqs = nqs, res = nes, rxs = nxs;
        __syncthreads();

        // ---- prefetch next ----
        if (n + 1 < NS_) {
            int n2 = n + 1, chunk2 = bh*NS_ + n2;
            const float* qrow = qin + rowbase + (size_t)(n2*16 + c16)*DIM_;
            const float* krow = kin + rowbase + (size_t)(n2*16 + c16)*DIM_;
            qr = ((const float4*)qrow)[l32];
            kr = ((const float4*)krow)[l32];
            if (l32 < 16)
                vr = ((const float2*)(vin + rowbase + (size_t)(n2*16 + c16)*DIM_ + et*ET_))[l32];
            if (tid < 256) cE = g_E[chunk2*256 + tid];
            if (tid < 16) { cg_ = g_gexp[bh*S_ + n2*16 + tid]; cqs = g_qs[chunk2*16 + tid]; }
            if (tid >= 256) { nab_a = g_a[chunk2]; nab_b = g_b[chunk2]; }
            if (tid < 128) {
                int c = tid >> 3;
                nqs = g_qs[chunk2*16 + c];
                nes = g_esum[chunk2*16 + c];
                nxs = g_expns[chunk2*16 + c];
            }
        }

        float ks = 0.f;
        if (tid < 256) {
            // ---- inter: vectorized K-split q@Cp + pn + E@v ----
            ull acc[4][2];
            float pnp[4];
#pragma unroll
            for (int i = 0; i < 4; i++) { acc[i][0] = 0ull; acc[i][1] = 0ull; pnp[i] = 0.f; }
            int k0 = wid * 16;
#pragma unroll
            for (int kk4 = 0; kk4 < 4; kk4++) {
                int kb = k0 + kk4*4;
                float4 qreg[4];
#pragma unroll
                for (int i = 0; i < 4; i++)
                    qreg[i] = *(const float4*)&sq[cgi + 4*i][kb];
                float4 sn4 = *(const float4*)&sn[kb];
#pragma unroll
                for (int j = 0; j < 4; j++) {
                    ulonglong2 c2 = *(const ulonglong2*)&sC[kb + j][eg*4];
                    float snv = ((const float*)&sn4)[j];
#pragma unroll
                    for (int i = 0; i < 4; i++) {
                        float qv = ((const float*)&qreg[i])[j];
                        ull q2 = pk2(qv, qv);
                        acc[i][0] = ffma2(q2, c2.x, acc[i][0]);
                        acc[i][1] = ffma2(q2, c2.y, acc[i][1]);
                        pnp[i] = fmaf(qv, snv, pnp[i]);
                    }
                }
            }
#pragma unroll
            for (int i = 0; i < 4; i++) {
                float qsv = sqs[cgi + 4*i];
                ull q2 = pk2(qsv, qsv);
                acc[i][0] = fmul2(acc[i][0], q2);
                acc[i][1] = fmul2(acc[i][1], q2);
            }
#pragma unroll
            for (int rr = 0; rr < 2; rr++) {
                int r = wid*2 + rr;
                ulonglong2 v2 = *(const ulonglong2*)&sv[r][eg*4];
#pragma unroll
                for (int i = 0; i < 4; i++) {
                    float ev = sE[cgi + 4*i][r];
                    ull e2 = pk2(ev, ev);
                    acc[i][0] = ffma2(e2, v2.x, acc[i][0]);
                    acc[i][1] = ffma2(e2, v2.y, acc[i][1]);
                }
            }
#pragma unroll
            for (int i = 0; i < 4; i++) {
                ulonglong2 st; st.x = acc[i][0]; st.y = acc[i][1];
                *(ulonglong2*)&spart[wid][cgi + 4*i][eg*4] = st;
            }
            if (eg == 0) {
#pragma unroll
                for (int i = 0; i < 4; i++) spn[wid][cgi + 4*i] = pnp[i];
            }
        } else {
            // ---- update: Cf = a*Cf + b * k^T (v*gexp), packed ----
            float sgr[16];
#pragma unroll
            for (int i = 0; i < 4; i++) {
                float4 g4 = *(const float4*)&sgx[i*4];
                sgr[i*4+0]=g4.x; sgr[i*4+1]=g4.y; sgr[i*4+2]=g4.z; sgr[i*4+3]=g4.w;
            }
            ull acc2[8];
#pragma unroll
            for (int g = 0; g < 8; g++) acc2[g] = 0ull;
#pragma unroll
            for (int c = 0; c < 16; c++) {
                float2 v2 = *(const float2*)&sv[c][ux*2];
                float gv = sgr[c];
                ull vg = pk2(v2.x * gv, v2.y * gv);
                float4 ka = *(const float4*)&sk[c][uyy*8];
                float4 kb = *(const float4*)&sk[c][uyy*8 + 4];
                acc2[0] = ffma2(pk2(ka.x, ka.x), vg, acc2[0]);
                acc2[1] = ffma2(pk2(ka.y, ka.y), vg, acc2[1]);
                acc2[2] = ffma2(pk2(ka.z, ka.z), vg, acc2[2]);
                acc2[3] = ffma2(pk2(ka.w, ka.w), vg, acc2[3]);
                acc2[4] = ffma2(pk2(kb.x, kb.x), vg, acc2[4]);
                acc2[5] = ffma2(pk2(kb.y, kb.y), vg, acc2[5]);
                acc2[6] = ffma2(pk2(kb.z, kb.z), vg, acc2[6]);
                acc2[7] = ffma2(pk2(kb.w, kb.w), vg, acc2[7]);
            }
            ull a2 = pk2(av, av), b2 = pk2(bv, bv);
#pragma unroll
            for (int g = 0; g < 8; g++) {
                ull cur = pk2(Cf[g][0], Cf[g][1]);
                ull nw  = ffma2(cur, a2, fmul2(acc2[g], b2));
                float lo, hi;
                asm("mov.b64 {%0, %1}, %2;" : "=f"(lo), "=f"(hi) : "l"(nw));
                Cf[g][0] = lo; Cf[g][1] = hi;
            }
            if (utid < 128) {
#pragma unroll
                for (int c = 0; c < 16; c++)
                    ks = fmaf(sk[c][utid], sgr[c], ks);
            }
        }
        __syncthreads();

        if (tid < 128) {
            // ---- reduce partials + norm + store h ----
            int c = tid >> 3, eq = tid & 7;
            float4 hs = make_float4(0.f, 0.f, 0.f, 0.f);
#pragma unroll
            for (int w = 0; w < 8; w++) {
                float4 p = *(const float4*)&spart[w][c][eq*4];
                hs.x += p.x; hs.y += p.y; hs.z += p.z; hs.w += p.w;
            }
            float pn = 0.f;
#pragma unroll
            for (int w = 0; w < 8; w++) pn += spn[w][c];
            float norm = fmaxf(fabsf(res + rqs*pn), rxs) + EPS_;
            float inv = 1.f / norm;
            hs.x *= inv; hs.y *= inv; hs.z *= inv; hs.w *= inv;
            *(float4*)(out + rowbase + (size_t)(n*16 + c)*DIM_ + et*ET_ + eq*4) = hs;
        } else if (tid >= 256) {
#pragma unroll
            for (int g = 0; g < 8; g++)
                *(float2*)&sC[uyy*8 + g][ux*2] = make_float2(Cf[g][0], Cf[g][1]);
            if (utid < 128)
                sn[utid] = fmaf(sn[utid], av, ks * bv);
        }
    }

    // ---- final states ----
    if (tid >= 256) {
        size_t clb = (size_t)bh * (DH_*DH_);
#pragma unroll
        for (int g = 0; g < 8; g++) {
            size_t o = clb + (size_t)(uyy*8 + g)*DH_ + et*ET_ + ux*2;
            *(float2*)&Cl[o] = make_float2(Cf[g][0], Cf[g][1]);
        }
        if (et == 0 && utid < 128) nl[bh*DH_ + utid] = sn[utid];
    }
}

// ============================================================
// K5: in-place layernorm over out, per (b,s,head) row of 128.
// ============================================================
__global__ __launch_bounds__(256) void k_ln(
    const float* __restrict__ lnw, const float* __restrict__ lnb,
    float* __restrict__ out)
{
    int r = blockIdx.x*8 + (threadIdx.x >> 5);
    int lane = threadIdx.x & 31;
    int bs = r >> 3, h = r & 7;
    float4* p = (float4*)(out + (size_t)bs*DIM_ + h*DH_);
    float4 x = p[lane];
    float s1 = x.x + x.y + x.z + x.w;
#pragma unroll
    for (int off = 16; off; off >>= 1)
        s1 += __shfl_xor_sync(0xffffffffu, s1, off);
    float mu = s1 * (1.f/128.f);
    float dx = x.x - mu, dy = x.y - mu, dz = x.z - mu, dw = x.w - mu;
    float s2 = dx*dx + dy*dy + dz*dz + dw*dw;
#pragma unroll
    for (int off = 16; off; off >>= 1)
        s2 += __shfl_xor_sync(0xffffffffu, s2, off);
    float rstd = rsqrtf(s2 * (1.f/128.f) + LN_EPS_);
    float4 w = ((const float4*)(lnw + h*DH_))[lane];
    float4 bb = ((const float4*)(lnb + h*DH_))[lane];
    x.x = dx*rstd*(1.f + w.x) + bb.x;
    x.y = dy*rstd*(1.f + w.y) + bb.y;
    x.z = dz*rstd*(1.f + w.z) + bb.z;
    x.w = dw*rstd*(1.f + w.w) + bb.w;
    p[lane] = x;
}

// ============================================================
extern "C" void kernel_launch(void* const* d_in, const int* in_sizes, int n_in,
                              void* d_out, int out_size)
{
    const float* q   = (const float*)d_in[0];
    const float* k   = (const float*)d_in[1];
    const float* v   = (const float*)d_in[2];
    const float* Wi  = (const float*)d_in[3];
    const float* bi  = (const float*)d_in[4];
    const float* Wf  = (const float*)d_in[5];
    const float* bf  = (const float*)d_in[6];
    const float* lnw = (const float*)d_in[7];
    const float* lnb = (const float*)d_in[8];

    float* out = (float*)d_out;
    float* Cl  = out + (size_t)B_*S_*DIM_;
    float* nl  = Cl  + (size_t)BH_*DH_*DH_;
    float* ml  = nl  + (size_t)BH_*DH_;

    k_gates  <<< (B_*S_)/K1_T, 256 >>>(q, k, v, Wi, bi, Wf, bf);
    k_prep   <<< BH_, 128 >>>(ml);
    k_phaseA <<< NCHUNK, 128 >>>(q, k);
    dim3 gf(4, BH_);
    k_fused5 <<< gf, 512 >>>(q, k, v, out, Cl, nl);
    k_ln     <<< (B_*S_*NH_)/8, 256 >>>(lnw, lnb, out);
}